// round 1
// baseline (speedup 1.0000x reference)
#include <cuda_runtime.h>
#include <cuda_bf16.h>
#include <math.h>
#include <stdint.h>

// Problem constants
#define BB 64
#define KK 512
#define MM 512
#define DD 256
#define NI 15
#define MI 3
// rows per side
#define RQ (BB*KK)          // 32768
#define RTOT (2*RQ)         // 65536
#define PLANE ((size_t)KK*MM)  // 262144 per batch
#define TOTE ((size_t)BB*PLANE) // 16777216

// ---------------- device scratch (static; no allocation) ----------------
__device__ float g_H[2*(size_t)RQ*DD];   // hidden activations (q then r)
__device__ float g_P[2*(size_t)RQ*DD];   // projections (q then r)
__device__ float g_E[TOTE];              // stabilized kernel matrix
__device__ float g_q2[RQ], g_r2[RQ];
__device__ float g_logmu[RQ], g_lognu[RQ], g_rowRef[RQ];
__device__ float g_la[RQ], g_lb[RQ];
__device__ float g_colsum[3*RQ];
__device__ float g_cvec[BB];

// ---------------- fast exp on FMA pipe ----------------
__device__ __forceinline__ float fexp(float x) {
    x = fminf(fmaxf(x, -87.0f), 88.0f);
    const float L2E    = 1.4426950408889634f;   // rounds to 0x3FB8AA3B
    const float L2E_LO = 1.9259629911e-8f;
    float t  = fmaf(x, L2E, 12582912.0f);       // round-to-nearest via magic
    float kf = t - 12582912.0f;
    float r  = fmaf(x, L2E, -kf);
    r = fmaf(x, L2E_LO, r);
    // 2^r, |r|<=0.5, Taylor deg-6 (~1e-7 rel)
    float p = 1.5403530e-4f;
    p = fmaf(p, r, 1.33335581e-3f);
    p = fmaf(p, r, 9.61812911e-3f);
    p = fmaf(p, r, 5.55041087e-2f);
    p = fmaf(p, r, 2.40226507e-1f);
    p = fmaf(p, r, 6.93147182e-1f);
    p = fmaf(p, r, 1.0f);
    int ei = (int)kf;
    float s = __int_as_float((ei + 127) << 23);
    return p * s;
}

// ---------------- projection GEMM: Y[r,n] = act(sum_k X[r,k]*W[n,k] + b[n]) ----------------
// BM=128 BN=64 BK=16, 256 threads, per-thread 8x4
__global__ void __launch_bounds__(256) proj_gemm(const float* __restrict__ X,
                                                 const float* __restrict__ W,
                                                 const float* __restrict__ bias,
                                                 float* __restrict__ Y,
                                                 int relu) {
    __shared__ float Xs[16][132];
    __shared__ float Ws[16][68];
    int m0 = blockIdx.x * 128;
    int n0 = blockIdx.y * 64;
    int t = threadIdx.x;
    int tx = t & 15, ty = t >> 4;
    float acc[8][4];
#pragma unroll
    for (int i = 0; i < 8; i++)
#pragma unroll
        for (int j = 0; j < 4; j++) acc[i][j] = 0.f;

    for (int k0 = 0; k0 < DD; k0 += 16) {
#pragma unroll
        for (int i = 0; i < 2; i++) {
            int idx = t + 256 * i;
            int row = idx >> 2;
            int kq  = (idx & 3) * 4;
            float4 v = *(const float4*)&X[(size_t)(m0 + row) * DD + k0 + kq];
            Xs[kq+0][row] = v.x; Xs[kq+1][row] = v.y;
            Xs[kq+2][row] = v.z; Xs[kq+3][row] = v.w;
        }
        {
            int row = t >> 2;
            int kq  = (t & 3) * 4;
            float4 v = *(const float4*)&W[(size_t)(n0 + row) * DD + k0 + kq];
            Ws[kq+0][row] = v.x; Ws[kq+1][row] = v.y;
            Ws[kq+2][row] = v.z; Ws[kq+3][row] = v.w;
        }
        __syncthreads();
#pragma unroll
        for (int kk = 0; kk < 16; kk++) {
            float a[8], b[4];
            *(float4*)&a[0] = *(const float4*)&Xs[kk][ty * 8];
            *(float4*)&a[4] = *(const float4*)&Xs[kk][ty * 8 + 4];
            *(float4*)&b[0] = *(const float4*)&Ws[kk][tx * 4];
#pragma unroll
            for (int i = 0; i < 8; i++)
#pragma unroll
                for (int j = 0; j < 4; j++) acc[i][j] = fmaf(a[i], b[j], acc[i][j]);
        }
        __syncthreads();
    }
    float4 bb = *(const float4*)&bias[n0 + tx * 4];
#pragma unroll
    for (int i = 0; i < 8; i++) {
        float4 o;
        o.x = acc[i][0] + bb.x; o.y = acc[i][1] + bb.y;
        o.z = acc[i][2] + bb.z; o.w = acc[i][3] + bb.w;
        if (relu) {
            o.x = fmaxf(o.x, 0.f); o.y = fmaxf(o.y, 0.f);
            o.z = fmaxf(o.z, 0.f); o.w = fmaxf(o.w, 0.f);
        }
        *(float4*)&Y[(size_t)(m0 + ty * 8 + i) * DD + n0 + tx * 4] = o;
    }
}

// ---------------- row squared norms of g_P ----------------
__global__ void __launch_bounds__(256) rownorm_kernel() {
    int r = blockIdx.x * 8 + (threadIdx.x >> 5);
    int lane = threadIdx.x & 31;
    const float4* row = (const float4*)(g_P + (size_t)r * DD);
    float s = 0.f;
#pragma unroll
    for (int c = 0; c < 2; c++) {
        float4 v = row[lane + 32 * c];
        s += v.x * v.x + v.y * v.y + v.z * v.z + v.w * v.w;
    }
#pragma unroll
    for (int o = 16; o; o >>= 1) s += __shfl_xor_sync(~0u, s, o);
    if (lane == 0) {
        if (r < RQ) g_q2[r] = s; else g_r2[r - RQ] = s;
    }
}

// ---------------- prep: logmu/lognu, zero buffers ----------------
__global__ void __launch_bounds__(512) prep_kernel(const float* __restrict__ mq,
                                                   const float* __restrict__ mr) {
    __shared__ float red[512];
    int b = blockIdx.x, t = threadIdx.x;
    float vq = mq[b * 512 + t];
    red[t] = vq; __syncthreads();
    for (int s = 256; s; s >>= 1) { if (t < s) red[t] += red[t + s]; __syncthreads(); }
    float smq = red[0]; __syncthreads();
    g_logmu[b * 512 + t] = logf(fmaxf(vq / (smq + 1e-8f), 1e-8f));

    float vr = mr[b * 512 + t];
    red[t] = vr; __syncthreads();
    for (int s = 256; s; s >>= 1) { if (t < s) red[t] += red[t + s]; __syncthreads(); }
    float smr = red[0]; __syncthreads();
    g_lognu[b * 512 + t] = logf(fmaxf(vr / (smr + 1e-8f), 1e-8f));

    g_lb[b * 512 + t] = 0.f;
    g_la[b * 512 + t] = 0.f;
    g_colsum[0 * RQ + b * 512 + t] = 0.f;
    g_colsum[1 * RQ + b * 512 + t] = 0.f;
    g_colsum[2 * RQ + b * 512 + t] = 0.f;
    if (t == 0) g_cvec[b] = 0.f;
}

// ---------------- cross batched GEMM -> C = sqrt(max(q2+r2-2*dot, 1e-6)) ----------------
__global__ void __launch_bounds__(256) cross_kernel(float* __restrict__ Cout) {
    __shared__ float As[16][68];
    __shared__ float Bs[16][68];
    int b = blockIdx.z;
    int m0 = blockIdx.x * 64;
    int n0 = blockIdx.y * 64;
    const float* A = g_P + (size_t)b * KK * DD;
    const float* Bp = g_P + (size_t)RQ * DD + (size_t)b * MM * DD;
    int t = threadIdx.x;
    int tx = t & 15, ty = t >> 4;
    float acc[4][4];
#pragma unroll
    for (int i = 0; i < 4; i++)
#pragma unroll
        for (int j = 0; j < 4; j++) acc[i][j] = 0.f;

    for (int k0 = 0; k0 < DD; k0 += 16) {
        int row = t >> 2;
        int kq  = (t & 3) * 4;
        float4 va = *(const float4*)&A[(size_t)(m0 + row) * DD + k0 + kq];
        As[kq+0][row] = va.x; As[kq+1][row] = va.y; As[kq+2][row] = va.z; As[kq+3][row] = va.w;
        float4 vb = *(const float4*)&Bp[(size_t)(n0 + row) * DD + k0 + kq];
        Bs[kq+0][row] = vb.x; Bs[kq+1][row] = vb.y; Bs[kq+2][row] = vb.z; Bs[kq+3][row] = vb.w;
        __syncthreads();
#pragma unroll
        for (int kk = 0; kk < 16; kk++) {
            float a[4], bb[4];
            *(float4*)&a[0]  = *(const float4*)&As[kk][ty * 4];
            *(float4*)&bb[0] = *(const float4*)&Bs[kk][tx * 4];
#pragma unroll
            for (int i = 0; i < 4; i++)
#pragma unroll
                for (int j = 0; j < 4; j++) acc[i][j] = fmaf(a[i], bb[j], acc[i][j]);
        }
        __syncthreads();
    }
    float r2v[4];
#pragma unroll
    for (int j = 0; j < 4; j++) r2v[j] = g_r2[b * 512 + n0 + tx * 4 + j];
#pragma unroll
    for (int i = 0; i < 4; i++) {
        float q2v = g_q2[b * 512 + m0 + ty * 4 + i];
        float4 o;
        o.x = sqrtf(fmaxf(q2v + r2v[0] - 2.f * acc[i][0], 1e-6f));
        o.y = sqrtf(fmaxf(q2v + r2v[1] - 2.f * acc[i][1], 1e-6f));
        o.z = sqrtf(fmaxf(q2v + r2v[2] - 2.f * acc[i][2], 1e-6f));
        o.w = sqrtf(fmaxf(q2v + r2v[3] - 2.f * acc[i][3], 1e-6f));
        *(float4*)&Cout[((size_t)b * 512 + m0 + ty * 4 + i) * 512 + n0 + tx * 4] = o;
    }
}

// ---------------- build E = exp(-20C + lognu - rowRef), rowRef = rowmax ----------------
__global__ void __launch_bounds__(256) ebuild_kernel(const float* __restrict__ C) {
    int wid = threadIdx.x >> 5, lane = threadIdx.x & 31;
    int gid = blockIdx.x * 8 + wid;      // row id 0..32767
    int b = gid >> 9;
    size_t base = (size_t)gid * 512;
    const float4* Crow = (const float4*)(C + base);
    const float4* Nu   = (const float4*)(g_lognu + (size_t)b * 512);
    float4 v4[4];
    float mx = -1e30f;
#pragma unroll
    for (int c = 0; c < 4; c++) {
        float4 cc = Crow[lane + 32 * c];
        float4 nu = Nu[lane + 32 * c];
        float4 v;
        v.x = fmaf(cc.x, -20.f, nu.x);
        v.y = fmaf(cc.y, -20.f, nu.y);
        v.z = fmaf(cc.z, -20.f, nu.z);
        v.w = fmaf(cc.w, -20.f, nu.w);
        v4[c] = v;
        mx = fmaxf(mx, fmaxf(fmaxf(v.x, v.y), fmaxf(v.z, v.w)));
    }
#pragma unroll
    for (int o = 16; o; o >>= 1) mx = fmaxf(mx, __shfl_xor_sync(~0u, mx, o));
    float4* Erow = (float4*)(g_E + base);
#pragma unroll
    for (int c = 0; c < 4; c++) {
        float4 e;
        e.x = fexp(v4[c].x - mx); e.y = fexp(v4[c].y - mx);
        e.z = fexp(v4[c].z - mx); e.w = fexp(v4[c].w - mx);
        Erow[lane + 32 * c] = e;
    }
    if (lane == 0) g_rowRef[gid] = mx;
}

// ---------------- Sinkhorn row pass: la = -(logmu + rowRef + sb + log(E @ vb)) ----------------
__global__ void __launch_bounds__(256) row_pass() {
    __shared__ float vb[512];
    __shared__ float red[256];
    int b = blockIdx.x >> 3, r0 = (blockIdx.x & 7) * 64;
    int t = threadIdx.x;
    float l0 = g_lb[b * 512 + t], l1 = g_lb[b * 512 + 256 + t];
    red[t] = fmaxf(l0, l1); __syncthreads();
    for (int s = 128; s; s >>= 1) { if (t < s) red[t] = fmaxf(red[t], red[t + s]); __syncthreads(); }
    float sb = red[0]; __syncthreads();
    vb[t] = fexp(l0 - sb); vb[t + 256] = fexp(l1 - sb);
    __syncthreads();
    int wid = t >> 5, lane = t & 31;
    for (int rr = wid; rr < 64; rr += 8) {
        int k = r0 + rr;
        size_t base = ((size_t)b * 512 + k) * 512;
        const float4* Erow = (const float4*)(g_E + base);
        const float4* W = (const float4*)vb;
        float acc = 0.f;
#pragma unroll
        for (int c = 0; c < 4; c++) {
            float4 e = Erow[lane + 32 * c];
            float4 w = W[lane + 32 * c];
            acc += e.x * w.x + e.y * w.y + e.z * w.z + e.w * w.w;
        }
#pragma unroll
        for (int o = 16; o; o >>= 1) acc += __shfl_xor_sync(~0u, acc, o);
        if (lane == 0)
            g_la[b * 512 + k] = -(g_logmu[b * 512 + k] + g_rowRef[b * 512 + k] + sb +
                                  logf(fmaxf(acc, 1e-35f)));
    }
}

// ---------------- Sinkhorn col pass: lb = -(sa + log(E^T @ wa)), wa=exp(g-sa), g=logmu+rowRef+la ----------------
__global__ void __launch_bounds__(256) col_pass() {
    __shared__ float wa[512];
    __shared__ float red[256];
    __shared__ float part[256];
    int b = blockIdx.x >> 3, c0 = (blockIdx.x & 7) * 64;
    int t = threadIdx.x;
    float g0 = g_logmu[b * 512 + t] + g_rowRef[b * 512 + t] + g_la[b * 512 + t];
    float g1 = g_logmu[b * 512 + 256 + t] + g_rowRef[b * 512 + 256 + t] + g_la[b * 512 + 256 + t];
    red[t] = fmaxf(g0, g1); __syncthreads();
    for (int s = 128; s; s >>= 1) { if (t < s) red[t] = fmaxf(red[t], red[t + s]); __syncthreads(); }
    float sa = red[0]; __syncthreads();
    wa[t] = fexp(g0 - sa); wa[t + 256] = fexp(g1 - sa);
    __syncthreads();
    int col = t & 63, kg = t >> 6;
    float acc = 0.f;
    size_t base = ((size_t)b * 512) * 512 + c0 + col;
#pragma unroll 4
    for (int k = kg; k < 512; k += 4)
        acc = fmaf(g_E[base + (size_t)k * 512], wa[k], acc);
    part[t] = acc; __syncthreads();
    if (t < 64) {
        float s = part[t] + part[t + 64] + part[t + 128] + part[t + 192];
        g_lb[b * 512 + c0 + t] = -(sa + logf(fmaxf(s, 1e-35f)));
    }
}

// ---------------- MI pass A: T <- (src)^2 / rowsum ; accumulate colsums ----------------
__global__ void __launch_bounds__(256) mi_passA(float* __restrict__ T, int it) {
    __shared__ float rb[512];
    __shared__ float cs[512];
    int b = blockIdx.x >> 3, r0 = (blockIdx.x & 7) * 64;
    int t = threadIdx.x;
    for (int i = t; i < 512; i += 256) {
        rb[i] = (it == 0) ? fexp(g_lb[b * 512 + i]) : 0.f;
        cs[i] = 0.f;
    }
    __syncthreads();
    int wid = t >> 5, lane = t & 31;
    for (int rr = wid; rr < 64; rr += 8) {
        int k = r0 + rr;
        size_t base = ((size_t)b * 512 + k) * 512;
        float ra = 0.f;
        if (it == 0)
            ra = fexp(g_logmu[b * 512 + k] + g_rowRef[b * 512 + k] + g_la[b * 512 + k]);
        float4 tv[4];
        float rs = 0.f;
#pragma unroll
        for (int c = 0; c < 4; c++) {
            int off = lane + 32 * c;
            float4 x;
            if (it == 0) {
                float4 e = ((const float4*)(g_E + base))[off];
                float4 r4 = ((const float4*)rb)[off];
                x.x = e.x * ra * r4.x; x.y = e.y * ra * r4.y;
                x.z = e.z * ra * r4.z; x.w = e.w * ra * r4.w;
            } else {
                x = ((const float4*)(T + base))[off];
            }
            x.x *= x.x; x.y *= x.y; x.z *= x.z; x.w *= x.w;
            tv[c] = x;
            rs += x.x + x.y + x.z + x.w;
        }
#pragma unroll
        for (int o = 16; o; o >>= 1) rs += __shfl_xor_sync(~0u, rs, o);
        float inv = 1.0f / (rs + 1e-8f);
#pragma unroll
        for (int c = 0; c < 4; c++) {
            int off = lane + 32 * c;
            float4 o4;
            o4.x = tv[c].x * inv; o4.y = tv[c].y * inv;
            o4.z = tv[c].z * inv; o4.w = tv[c].w * inv;
            ((float4*)(T + base))[off] = o4;
            int m = off * 4;
            atomicAdd(&cs[m + 0], o4.x); atomicAdd(&cs[m + 1], o4.y);
            atomicAdd(&cs[m + 2], o4.z); atomicAdd(&cs[m + 3], o4.w);
        }
    }
    __syncthreads();
    for (int i = t; i < 512; i += 256)
        atomicAdd(&g_colsum[(size_t)it * RQ + b * 512 + i], cs[i]);
}

// ---------------- MI pass B: T <- T / colsum ; last: c += T*C ----------------
__global__ void __launch_bounds__(256) mi_passB(float* __restrict__ T,
                                                const float* __restrict__ C,
                                                int it, int last) {
    __shared__ float inv[512];
    __shared__ float red[8];
    int b = blockIdx.x >> 3, r0 = (blockIdx.x & 7) * 64;
    int t = threadIdx.x;
    for (int i = t; i < 512; i += 256)
        inv[i] = 1.0f / (g_colsum[(size_t)it * RQ + b * 512 + i] + 1e-8f);
    __syncthreads();
    int wid = t >> 5, lane = t & 31;
    float cacc = 0.f;
    for (int rr = wid; rr < 64; rr += 8) {
        int k = r0 + rr;
        size_t base = ((size_t)b * 512 + k) * 512;
#pragma unroll
        for (int c = 0; c < 4; c++) {
            int off = lane + 32 * c;
            float4 x = ((const float4*)(T + base))[off];
            float4 iv = ((const float4*)inv)[off];
            x.x *= iv.x; x.y *= iv.y; x.z *= iv.z; x.w *= iv.w;
            ((float4*)(T + base))[off] = x;
            if (last) {
                float4 cc = ((const float4*)(C + base))[off];
                cacc += x.x * cc.x + x.y * cc.y + x.z * cc.z + x.w * cc.w;
            }
        }
    }
    if (last) {
#pragma unroll
        for (int o = 16; o; o >>= 1) cacc += __shfl_xor_sync(~0u, cacc, o);
        if (lane == 0) red[wid] = cacc;
        __syncthreads();
        if (t == 0) {
            float s = 0.f;
#pragma unroll
            for (int w = 0; w < 8; w++) s += red[w];
            atomicAdd(&g_cvec[b], s);
        }
    }
}

// ---------------- finalize: sim = sigmoid(-c) ----------------
__global__ void finalize_kernel(float* __restrict__ sim, float* __restrict__ outc) {
    int b = threadIdx.x;
    if (b < BB) {
        float c = g_cvec[b];
        outc[b] = c;
        sim[b] = 1.0f / (1.0f + expf(c));
    }
}

// ---------------- launch ----------------
extern "C" void kernel_launch(void* const* d_in, const int* in_sizes, int n_in,
                              void* d_out, int out_size) {
    const float* sq = (const float*)d_in[0];
    const float* sr = (const float*)d_in[1];
    const float* mq = (const float*)d_in[2];
    const float* mr = (const float*)d_in[3];
    const float* W1 = (const float*)d_in[4];
    const float* b1 = (const float*)d_in[5];
    const float* W2 = (const float*)d_in[6];
    const float* b2 = (const float*)d_in[7];

    float* out = (float*)d_out;
    float* out_sim = out;                       // [64]
    float* out_T   = out + BB;                  // [64*512*512]
    float* out_C   = out + BB + TOTE;           // [64*512*512]
    float* out_c   = out + BB + 2 * TOTE;       // [64]

    float* Hq; cudaGetSymbolAddress((void**)&Hq, g_H);
    float* Pq; cudaGetSymbolAddress((void**)&Pq, g_P);
    float* Hr = Hq + (size_t)RQ * DD;
    float* Pr = Pq + (size_t)RQ * DD;

    dim3 gridProj(RQ / 128, DD / 64);
    // layer 1 (ReLU)
    proj_gemm<<<gridProj, 256>>>(sq, W1, b1, Hq, 1);
    proj_gemm<<<gridProj, 256>>>(sr, W1, b1, Hr, 1);
    // layer 2
    proj_gemm<<<gridProj, 256>>>(Hq, W2, b2, Pq, 0);
    proj_gemm<<<gridProj, 256>>>(Hr, W2, b2, Pr, 0);

    rownorm_kernel<<<RTOT / 8, 256>>>();
    prep_kernel<<<BB, 512>>>(mq, mr);

    cross_kernel<<<dim3(8, 8, BB), 256>>>(out_C);
    ebuild_kernel<<<RQ / 8, 256>>>(out_C);

    for (int i = 0; i < NI; i++) {
        row_pass<<<BB * 8, 256>>>();
        col_pass<<<BB * 8, 256>>>();
    }

    for (int it = 0; it < MI; it++) {
        mi_passA<<<BB * 8, 256>>>(out_T, it);
        mi_passB<<<BB * 8, 256>>>(out_T, out_C, it, it == MI - 1 ? 1 : 0);
    }

    finalize_kernel<<<1, 64>>>(out_sim, out_c);
}

// round 2
// speedup vs baseline: 1.2501x; 1.2501x over previous
#include <cuda_runtime.h>
#include <cuda_bf16.h>
#include <math.h>
#include <stdint.h>

// Problem constants
#define BB 64
#define KK 512
#define MM 512
#define DD 256
#define NI 15
#define MI 3
#define RQ (BB*KK)              // 32768
#define RTOT (2*RQ)             // 65536
#define PLANE ((size_t)KK*MM)
#define TOTE ((size_t)BB*PLANE) // 16777216

// ---------------- device scratch (static; no allocation) ----------------
__device__ float g_H[2*(size_t)RQ*DD];
__device__ float g_P[2*(size_t)RQ*DD];
__device__ float g_E[TOTE];
__device__ float g_q2[RQ], g_r2[RQ];
__device__ float g_logmu[RQ], g_lognu[RQ], g_rowRef[RQ];
__device__ float g_la[RQ], g_lb[RQ];
__device__ float g_colsum[3*RQ];
__device__ float g_cvec[BB];

// ---------------- fast exp on FMA pipe ----------------
__device__ __forceinline__ float fexp(float x) {
    x = fminf(fmaxf(x, -87.0f), 88.0f);
    const float L2E    = 1.4426950408889634f;
    const float L2E_LO = 1.9259629911e-8f;
    float t  = fmaf(x, L2E, 12582912.0f);
    float kf = t - 12582912.0f;
    float r  = fmaf(x, L2E, -kf);
    r = fmaf(x, L2E_LO, r);
    float p = 1.5403530e-4f;
    p = fmaf(p, r, 1.33335581e-3f);
    p = fmaf(p, r, 9.61812911e-3f);
    p = fmaf(p, r, 5.55041087e-2f);
    p = fmaf(p, r, 2.40226507e-1f);
    p = fmaf(p, r, 6.93147182e-1f);
    p = fmaf(p, r, 1.0f);
    int ei = (int)kf;
    float s = __int_as_float((ei + 127) << 23);
    return p * s;
}

// ============================================================================
// 128x128 GEMM core, BK=8, 256 threads, 8x8 per-thread tile (split 4+4 at +64)
// smem ping-pong with ONE __syncthreads per k-iteration
// ============================================================================

// Y[r,n] = act(sum_k X[r,k] * W[n,k] + b[n]);  X:[M,256], W:[N,256] row-major
__global__ void __launch_bounds__(256, 2) proj_gemm(const float* __restrict__ X,
                                                    const float* __restrict__ W,
                                                    const float* __restrict__ bias,
                                                    float* __restrict__ Y,
                                                    int relu) {
    __shared__ float As[2][8][128];
    __shared__ float Bs[2][8][128];
    int m0 = blockIdx.x * 128;
    int n0 = blockIdx.y * 128;
    int t = threadIdx.x;
    int tx = t & 15, ty = t >> 4;
    int lrow = t >> 1, lk = (t & 1) * 4;

    const float* Aptr = X + (size_t)(m0 + lrow) * DD + lk;
    const float* Bptr = W + (size_t)(n0 + lrow) * DD + lk;

    float acc[8][8];
#pragma unroll
    for (int i = 0; i < 8; i++)
#pragma unroll
        for (int j = 0; j < 8; j++) acc[i][j] = 0.f;

    float4 ra = *(const float4*)Aptr;
    float4 rb = *(const float4*)Bptr;
    As[0][lk+0][lrow] = ra.x; As[0][lk+1][lrow] = ra.y;
    As[0][lk+2][lrow] = ra.z; As[0][lk+3][lrow] = ra.w;
    Bs[0][lk+0][lrow] = rb.x; Bs[0][lk+1][lrow] = rb.y;
    Bs[0][lk+2][lrow] = rb.z; Bs[0][lk+3][lrow] = rb.w;
    __syncthreads();

    int buf = 0;
#pragma unroll 1
    for (int kb = 0; kb < 32; kb++) {
        if (kb < 31) {
            ra = *(const float4*)(Aptr + (kb + 1) * 8);
            rb = *(const float4*)(Bptr + (kb + 1) * 8);
        }
#pragma unroll
        for (int kk = 0; kk < 8; kk++) {
            float a[8], b[8];
            *(float4*)&a[0] = *(const float4*)&As[buf][kk][ty * 4];
            *(float4*)&a[4] = *(const float4*)&As[buf][kk][ty * 4 + 64];
            *(float4*)&b[0] = *(const float4*)&Bs[buf][kk][tx * 4];
            *(float4*)&b[4] = *(const float4*)&Bs[buf][kk][tx * 4 + 64];
#pragma unroll
            for (int i = 0; i < 8; i++)
#pragma unroll
                for (int j = 0; j < 8; j++) acc[i][j] = fmaf(a[i], b[j], acc[i][j]);
        }
        if (kb < 31) {
            buf ^= 1;
            As[buf][lk+0][lrow] = ra.x; As[buf][lk+1][lrow] = ra.y;
            As[buf][lk+2][lrow] = ra.z; As[buf][lk+3][lrow] = ra.w;
            Bs[buf][lk+0][lrow] = rb.x; Bs[buf][lk+1][lrow] = rb.y;
            Bs[buf][lk+2][lrow] = rb.z; Bs[buf][lk+3][lrow] = rb.w;
            __syncthreads();
        }
    }

    float4 bv0 = *(const float4*)&bias[n0 + tx * 4];
    float4 bv1 = *(const float4*)&bias[n0 + tx * 4 + 64];
#pragma unroll
    for (int hi = 0; hi < 2; hi++) {
#pragma unroll
        for (int i = 0; i < 4; i++) {
            int row = m0 + hi * 64 + ty * 4 + i;
            int ai = hi * 4 + i;
            float4 o0, o1;
            o0.x = acc[ai][0] + bv0.x; o0.y = acc[ai][1] + bv0.y;
            o0.z = acc[ai][2] + bv0.z; o0.w = acc[ai][3] + bv0.w;
            o1.x = acc[ai][4] + bv1.x; o1.y = acc[ai][5] + bv1.y;
            o1.z = acc[ai][6] + bv1.z; o1.w = acc[ai][7] + bv1.w;
            if (relu) {
                o0.x = fmaxf(o0.x, 0.f); o0.y = fmaxf(o0.y, 0.f);
                o0.z = fmaxf(o0.z, 0.f); o0.w = fmaxf(o0.w, 0.f);
                o1.x = fmaxf(o1.x, 0.f); o1.y = fmaxf(o1.y, 0.f);
                o1.z = fmaxf(o1.z, 0.f); o1.w = fmaxf(o1.w, 0.f);
            }
            *(float4*)&Y[(size_t)row * DD + n0 + tx * 4]      = o0;
            *(float4*)&Y[(size_t)row * DD + n0 + tx * 4 + 64] = o1;
        }
    }
}

// C[b,k,m] = sqrt(max(q2[k]+r2[m]-2*dot(Pq[k],Pr[m]), 1e-6)); 128x128 tiles
__global__ void __launch_bounds__(256, 2) cross_kernel(float* __restrict__ Cout) {
    __shared__ float As[2][8][128];
    __shared__ float Bs[2][8][128];
    int b = blockIdx.z;
    int m0 = blockIdx.x * 128;
    int n0 = blockIdx.y * 128;
    const float* A  = g_P + (size_t)b * KK * DD;
    const float* Bp = g_P + (size_t)RQ * DD + (size_t)b * MM * DD;
    int t = threadIdx.x;
    int tx = t & 15, ty = t >> 4;
    int lrow = t >> 1, lk = (t & 1) * 4;

    const float* Aptr = A  + (size_t)(m0 + lrow) * DD + lk;
    const float* Bptr = Bp + (size_t)(n0 + lrow) * DD + lk;

    float acc[8][8];
#pragma unroll
    for (int i = 0; i < 8; i++)
#pragma unroll
        for (int j = 0; j < 8; j++) acc[i][j] = 0.f;

    float4 ra = *(const float4*)Aptr;
    float4 rb = *(const float4*)Bptr;
    As[0][lk+0][lrow] = ra.x; As[0][lk+1][lrow] = ra.y;
    As[0][lk+2][lrow] = ra.z; As[0][lk+3][lrow] = ra.w;
    Bs[0][lk+0][lrow] = rb.x; Bs[0][lk+1][lrow] = rb.y;
    Bs[0][lk+2][lrow] = rb.z; Bs[0][lk+3][lrow] = rb.w;
    __syncthreads();

    int buf = 0;
#pragma unroll 1
    for (int kb = 0; kb < 32; kb++) {
        if (kb < 31) {
            ra = *(const float4*)(Aptr + (kb + 1) * 8);
            rb = *(const float4*)(Bptr + (kb + 1) * 8);
        }
#pragma unroll
        for (int kk = 0; kk < 8; kk++) {
            float a[8], bw[8];
            *(float4*)&a[0]  = *(const float4*)&As[buf][kk][ty * 4];
            *(float4*)&a[4]  = *(const float4*)&As[buf][kk][ty * 4 + 64];
            *(float4*)&bw[0] = *(const float4*)&Bs[buf][kk][tx * 4];
            *(float4*)&bw[4] = *(const float4*)&Bs[buf][kk][tx * 4 + 64];
#pragma unroll
            for (int i = 0; i < 8; i++)
#pragma unroll
                for (int j = 0; j < 8; j++) acc[i][j] = fmaf(a[i], bw[j], acc[i][j]);
        }
        if (kb < 31) {
            buf ^= 1;
            As[buf][lk+0][lrow] = ra.x; As[buf][lk+1][lrow] = ra.y;
            As[buf][lk+2][lrow] = ra.z; As[buf][lk+3][lrow] = ra.w;
            Bs[buf][lk+0][lrow] = rb.x; Bs[buf][lk+1][lrow] = rb.y;
            Bs[buf][lk+2][lrow] = rb.z; Bs[buf][lk+3][lrow] = rb.w;
            __syncthreads();
        }
    }

    float r2v[8];
#pragma unroll
    for (int j = 0; j < 4; j++) {
        r2v[j]     = g_r2[b * 512 + n0 + tx * 4 + j];
        r2v[j + 4] = g_r2[b * 512 + n0 + tx * 4 + 64 + j];
    }
#pragma unroll
    for (int hi = 0; hi < 2; hi++) {
#pragma unroll
        for (int i = 0; i < 4; i++) {
            int row = m0 + hi * 64 + ty * 4 + i;
            int ai = hi * 4 + i;
            float q2v = g_q2[b * 512 + row];
            float4 o0, o1;
            o0.x = sqrtf(fmaxf(q2v + r2v[0] - 2.f * acc[ai][0], 1e-6f));
            o0.y = sqrtf(fmaxf(q2v + r2v[1] - 2.f * acc[ai][1], 1e-6f));
            o0.z = sqrtf(fmaxf(q2v + r2v[2] - 2.f * acc[ai][2], 1e-6f));
            o0.w = sqrtf(fmaxf(q2v + r2v[3] - 2.f * acc[ai][3], 1e-6f));
            o1.x = sqrtf(fmaxf(q2v + r2v[4] - 2.f * acc[ai][4], 1e-6f));
            o1.y = sqrtf(fmaxf(q2v + r2v[5] - 2.f * acc[ai][5], 1e-6f));
            o1.z = sqrtf(fmaxf(q2v + r2v[6] - 2.f * acc[ai][6], 1e-6f));
            o1.w = sqrtf(fmaxf(q2v + r2v[7] - 2.f * acc[ai][7], 1e-6f));
            *(float4*)&Cout[((size_t)b * 512 + row) * 512 + n0 + tx * 4]      = o0;
            *(float4*)&Cout[((size_t)b * 512 + row) * 512 + n0 + tx * 4 + 64] = o1;
        }
    }
}

// ---------------- row squared norms of g_P ----------------
__global__ void __launch_bounds__(256) rownorm_kernel() {
    int r = blockIdx.x * 8 + (threadIdx.x >> 5);
    int lane = threadIdx.x & 31;
    const float4* row = (const float4*)(g_P + (size_t)r * DD);
    float s = 0.f;
#pragma unroll
    for (int c = 0; c < 2; c++) {
        float4 v = row[lane + 32 * c];
        s += v.x * v.x + v.y * v.y + v.z * v.z + v.w * v.w;
    }
#pragma unroll
    for (int o = 16; o; o >>= 1) s += __shfl_xor_sync(~0u, s, o);
    if (lane == 0) {
        if (r < RQ) g_q2[r] = s; else g_r2[r - RQ] = s;
    }
}

// ---------------- prep: logmu/lognu, zero buffers ----------------
__global__ void __launch_bounds__(512) prep_kernel(const float* __restrict__ mq,
                                                   const float* __restrict__ mr) {
    __shared__ float red[512];
    int b = blockIdx.x, t = threadIdx.x;
    float vq = mq[b * 512 + t];
    red[t] = vq; __syncthreads();
    for (int s = 256; s; s >>= 1) { if (t < s) red[t] += red[t + s]; __syncthreads(); }
    float smq = red[0]; __syncthreads();
    g_logmu[b * 512 + t] = logf(fmaxf(vq / (smq + 1e-8f), 1e-8f));

    float vr = mr[b * 512 + t];
    red[t] = vr; __syncthreads();
    for (int s = 256; s; s >>= 1) { if (t < s) red[t] += red[t + s]; __syncthreads(); }
    float smr = red[0]; __syncthreads();
    g_lognu[b * 512 + t] = logf(fmaxf(vr / (smr + 1e-8f), 1e-8f));

    g_lb[b * 512 + t] = 0.f;
    g_la[b * 512 + t] = 0.f;
    g_colsum[0 * RQ + b * 512 + t] = 0.f;
    g_colsum[1 * RQ + b * 512 + t] = 0.f;
    g_colsum[2 * RQ + b * 512 + t] = 0.f;
    if (t == 0) g_cvec[b] = 0.f;
}

// ---------------- build E = exp(-20C + lognu - rowmax) ----------------
__global__ void __launch_bounds__(256) ebuild_kernel(const float* __restrict__ C) {
    int wid = threadIdx.x >> 5, lane = threadIdx.x & 31;
    int gid = blockIdx.x * 8 + wid;
    int b = gid >> 9;
    size_t base = (size_t)gid * 512;
    const float4* Crow = (const float4*)(C + base);
    const float4* Nu   = (const float4*)(g_lognu + (size_t)b * 512);
    float4 v4[4];
    float mx = -1e30f;
#pragma unroll
    for (int c = 0; c < 4; c++) {
        float4 cc = Crow[lane + 32 * c];
        float4 nu = Nu[lane + 32 * c];
        float4 v;
        v.x = fmaf(cc.x, -20.f, nu.x);
        v.y = fmaf(cc.y, -20.f, nu.y);
        v.z = fmaf(cc.z, -20.f, nu.z);
        v.w = fmaf(cc.w, -20.f, nu.w);
        v4[c] = v;
        mx = fmaxf(mx, fmaxf(fmaxf(v.x, v.y), fmaxf(v.z, v.w)));
    }
#pragma unroll
    for (int o = 16; o; o >>= 1) mx = fmaxf(mx, __shfl_xor_sync(~0u, mx, o));
    float4* Erow = (float4*)(g_E + base);
#pragma unroll
    for (int c = 0; c < 4; c++) {
        float4 e;
        e.x = fexp(v4[c].x - mx); e.y = fexp(v4[c].y - mx);
        e.z = fexp(v4[c].z - mx); e.w = fexp(v4[c].w - mx);
        Erow[lane + 32 * c] = e;
    }
    if (lane == 0) g_rowRef[gid] = mx;
}

// ---------------- Sinkhorn row pass ----------------
__global__ void __launch_bounds__(256) row_pass() {
    __shared__ float vb[512];
    __shared__ float red[256];
    int b = blockIdx.x >> 3, r0 = (blockIdx.x & 7) * 64;
    int t = threadIdx.x;
    float l0 = g_lb[b * 512 + t], l1 = g_lb[b * 512 + 256 + t];
    red[t] = fmaxf(l0, l1); __syncthreads();
    for (int s = 128; s; s >>= 1) { if (t < s) red[t] = fmaxf(red[t], red[t + s]); __syncthreads(); }
    float sb = red[0]; __syncthreads();
    vb[t] = fexp(l0 - sb); vb[t + 256] = fexp(l1 - sb);
    __syncthreads();
    int wid = t >> 5, lane = t & 31;
    for (int rr = wid; rr < 64; rr += 8) {
        int k = r0 + rr;
        size_t base = ((size_t)b * 512 + k) * 512;
        const float4* Erow = (const float4*)(g_E + base);
        const float4* W = (const float4*)vb;
        float acc = 0.f;
#pragma unroll
        for (int c = 0; c < 4; c++) {
            float4 e = Erow[lane + 32 * c];
            float4 w = W[lane + 32 * c];
            acc += e.x * w.x + e.y * w.y + e.z * w.z + e.w * w.w;
        }
#pragma unroll
        for (int o = 16; o; o >>= 1) acc += __shfl_xor_sync(~0u, acc, o);
        if (lane == 0)
            g_la[b * 512 + k] = -(g_logmu[b * 512 + k] + g_rowRef[b * 512 + k] + sb +
                                  logf(fmaxf(acc, 1e-35f)));
    }
}

// ---------------- Sinkhorn col pass (vectorized) ----------------
__global__ void __launch_bounds__(256) col_pass() {
    __shared__ float wa[512];
    __shared__ float red[256];
    __shared__ float4 part[16][16];
    int b = blockIdx.x >> 3, c0 = (blockIdx.x & 7) * 64;
    int t = threadIdx.x;
    float g0 = g_logmu[b * 512 + t] + g_rowRef[b * 512 + t] + g_la[b * 512 + t];
    float g1 = g_logmu[b * 512 + 256 + t] + g_rowRef[b * 512 + 256 + t] + g_la[b * 512 + 256 + t];
    red[t] = fmaxf(g0, g1); __syncthreads();
    for (int s = 128; s; s >>= 1) { if (t < s) red[t] = fmaxf(red[t], red[t + s]); __syncthreads(); }
    float sa = red[0]; __syncthreads();
    wa[t] = fexp(g0 - sa); wa[t + 256] = fexp(g1 - sa);
    __syncthreads();
    int ci = t & 15, kg = t >> 4;
    float4 acc = {0.f, 0.f, 0.f, 0.f};
    const float* Ebase = g_E + (size_t)b * 512 * 512 + c0 + ci * 4;
#pragma unroll 4
    for (int k = kg; k < 512; k += 16) {
        float4 e = *(const float4*)(Ebase + (size_t)k * 512);
        float w = wa[k];
        acc.x = fmaf(e.x, w, acc.x); acc.y = fmaf(e.y, w, acc.y);
        acc.z = fmaf(e.z, w, acc.z); acc.w = fmaf(e.w, w, acc.w);
    }
    part[kg][ci] = acc;
    __syncthreads();
    if (t < 16) {
        float4 s = {0.f, 0.f, 0.f, 0.f};
#pragma unroll
        for (int g = 0; g < 16; g++) {
            float4 p = part[g][t];
            s.x += p.x; s.y += p.y; s.z += p.z; s.w += p.w;
        }
        int cbase = b * 512 + c0 + t * 4;
        g_lb[cbase + 0] = -(sa + logf(fmaxf(s.x, 1e-35f)));
        g_lb[cbase + 1] = -(sa + logf(fmaxf(s.y, 1e-35f)));
        g_lb[cbase + 2] = -(sa + logf(fmaxf(s.z, 1e-35f)));
        g_lb[cbase + 3] = -(sa + logf(fmaxf(s.w, 1e-35f)));
    }
}

// ---------------- MI it=0: T = rownorm((E*ra*rb)^2), colsum[0] ----------------
__global__ void __launch_bounds__(256) mi_first(float* __restrict__ T) {
    __shared__ float rb[512];
    __shared__ float cs[512];
    int b = blockIdx.x >> 3, r0 = (blockIdx.x & 7) * 64;
    int t = threadIdx.x;
    for (int i = t; i < 512; i += 256) {
        rb[i] = fexp(g_lb[b * 512 + i]);
        cs[i] = 0.f;
    }
    __syncthreads();
    int wid = t >> 5, lane = t & 31;
    float4 csum[4];
#pragma unroll
    for (int c = 0; c < 4; c++) csum[c] = make_float4(0.f, 0.f, 0.f, 0.f);
    for (int rr = wid; rr < 64; rr += 8) {
        int k = r0 + rr;
        size_t base = ((size_t)b * 512 + k) * 512;
        float ra = fexp(g_logmu[b * 512 + k] + g_rowRef[b * 512 + k] + g_la[b * 512 + k]);
        float4 tv[4];
        float rs = 0.f;
#pragma unroll
        for (int c = 0; c < 4; c++) {
            int off = lane + 32 * c;
            float4 e  = ((const float4*)(g_E + base))[off];
            float4 r4 = ((const float4*)rb)[off];
            float4 x;
            x.x = e.x * ra * r4.x; x.y = e.y * ra * r4.y;
            x.z = e.z * ra * r4.z; x.w = e.w * ra * r4.w;
            x.x *= x.x; x.y *= x.y; x.z *= x.z; x.w *= x.w;
            tv[c] = x;
            rs += x.x + x.y + x.z + x.w;
        }
#pragma unroll
        for (int o = 16; o; o >>= 1) rs += __shfl_xor_sync(~0u, rs, o);
        float inv = 1.0f / (rs + 1e-8f);
#pragma unroll
        for (int c = 0; c < 4; c++) {
            int off = lane + 32 * c;
            float4 o4;
            o4.x = tv[c].x * inv; o4.y = tv[c].y * inv;
            o4.z = tv[c].z * inv; o4.w = tv[c].w * inv;
            ((float4*)(T + base))[off] = o4;
            csum[c].x += o4.x; csum[c].y += o4.y;
            csum[c].z += o4.z; csum[c].w += o4.w;
        }
    }
#pragma unroll
    for (int c = 0; c < 4; c++) {
        int m = (lane + 32 * c) * 4;
        atomicAdd(&cs[m + 0], csum[c].x); atomicAdd(&cs[m + 1], csum[c].y);
        atomicAdd(&cs[m + 2], csum[c].z); atomicAdd(&cs[m + 3], csum[c].w);
    }
    __syncthreads();
    for (int i = t; i < 512; i += 256)
        atomicAdd(&g_colsum[b * 512 + i], cs[i]);
}

// ---------------- MI fused: T = rownorm((T/colsum[prev])^2), colsum[it] ----------------
__global__ void __launch_bounds__(256) mi_fused(float* __restrict__ T, int prev, int it) {
    __shared__ float inv[512];
    __shared__ float cs[512];
    int b = blockIdx.x >> 3, r0 = (blockIdx.x & 7) * 64;
    int t = threadIdx.x;
    for (int i = t; i < 512; i += 256) {
        inv[i] = 1.0f / (g_colsum[(size_t)prev * RQ + b * 512 + i] + 1e-8f);
        cs[i] = 0.f;
    }
    __syncthreads();
    int wid = t >> 5, lane = t & 31;
    float4 csum[4];
#pragma unroll
    for (int c = 0; c < 4; c++) csum[c] = make_float4(0.f, 0.f, 0.f, 0.f);
    for (int rr = wid; rr < 64; rr += 8) {
        int k = r0 + rr;
        size_t base = ((size_t)b * 512 + k) * 512;
        float4 tv[4];
        float rs = 0.f;
#pragma unroll
        for (int c = 0; c < 4; c++) {
            int off = lane + 32 * c;
            float4 x  = ((const float4*)(T + base))[off];
            float4 iv = ((const float4*)inv)[off];
            x.x *= iv.x; x.y *= iv.y; x.z *= iv.z; x.w *= iv.w;
            x.x *= x.x; x.y *= x.y; x.z *= x.z; x.w *= x.w;
            tv[c] = x;
            rs += x.x + x.y + x.z + x.w;
        }
#pragma unroll
        for (int o = 16; o; o >>= 1) rs += __shfl_xor_sync(~0u, rs, o);
        float rinv = 1.0f / (rs + 1e-8f);
#pragma unroll
        for (int c = 0; c < 4; c++) {
            int off = lane + 32 * c;
            float4 o4;
            o4.x = tv[c].x * rinv; o4.y = tv[c].y * rinv;
            o4.z = tv[c].z * rinv; o4.w = tv[c].w * rinv;
            ((float4*)(T + base))[off] = o4;
            csum[c].x += o4.x; csum[c].y += o4.y;
            csum[c].z += o4.z; csum[c].w += o4.w;
        }
    }
#pragma unroll
    for (int c = 0; c < 4; c++) {
        int m = (lane + 32 * c) * 4;
        atomicAdd(&cs[m + 0], csum[c].x); atomicAdd(&cs[m + 1], csum[c].y);
        atomicAdd(&cs[m + 2], csum[c].z); atomicAdd(&cs[m + 3], csum[c].w);
    }
    __syncthreads();
    for (int i = t; i < 512; i += 256)
        atomicAdd(&g_colsum[(size_t)it * RQ + b * 512 + i], cs[i]);
}

// ---------------- MI last: T = T/colsum[last]; c = sum(T*C) ----------------
__global__ void __launch_bounds__(256) mi_last(float* __restrict__ T,
                                               const float* __restrict__ C,
                                               int last) {
    __shared__ float inv[512];
    __shared__ float red[8];
    int b = blockIdx.x >> 3, r0 = (blockIdx.x & 7) * 64;
    int t = threadIdx.x;
    for (int i = t; i < 512; i += 256)
        inv[i] = 1.0f / (g_colsum[(size_t)last * RQ + b * 512 + i] + 1e-8f);
    __syncthreads();
    int wid = t >> 5, lane = t & 31;
    float cacc = 0.f;
    for (int rr = wid; rr < 64; rr += 8) {
        int k = r0 + rr;
        size_t base = ((size_t)b * 512 + k) * 512;
#pragma unroll
        for (int c = 0; c < 4; c++) {
            int off = lane + 32 * c;
            float4 x  = ((const float4*)(T + base))[off];
            float4 iv = ((const float4*)inv)[off];
            x.x *= iv.x; x.y *= iv.y; x.z *= iv.z; x.w *= iv.w;
            ((float4*)(T + base))[off] = x;
            float4 cc = ((const float4*)(C + base))[off];
            cacc += x.x * cc.x + x.y * cc.y + x.z * cc.z + x.w * cc.w;
        }
    }
#pragma unroll
    for (int o = 16; o; o >>= 1) cacc += __shfl_xor_sync(~0u, cacc, o);
    if (lane == 0) red[wid] = cacc;
    __syncthreads();
    if (t == 0) {
        float s = 0.f;
#pragma unroll
        for (int w = 0; w < 8; w++) s += red[w];
        atomicAdd(&g_cvec[b], s);
    }
}

// ---------------- finalize ----------------
__global__ void finalize_kernel(float* __restrict__ sim, float* __restrict__ outc) {
    int b = threadIdx.x;
    if (b < BB) {
        float c = g_cvec[b];
        outc[b] = c;
        sim[b] = 1.0f / (1.0f + expf(c));
    }
}

// ---------------- launch ----------------
extern "C" void kernel_launch(void* const* d_in, const int* in_sizes, int n_in,
                              void* d_out, int out_size) {
    const float* sq = (const float*)d_in[0];
    const float* sr = (const float*)d_in[1];
    const float* mq = (const float*)d_in[2];
    const float* mr = (const float*)d_in[3];
    const float* W1 = (const float*)d_in[4];
    const float* b1 = (const float*)d_in[5];
    const float* W2 = (const float*)d_in[6];
    const float* b2 = (const float*)d_in[7];

    float* out = (float*)d_out;
    float* out_sim = out;
    float* out_T   = out + BB;
    float* out_C   = out + BB + TOTE;
    float* out_c   = out + BB + 2 * TOTE;

    float* Hq; cudaGetSymbolAddress((void**)&Hq, g_H);
    float* Pq; cudaGetSymbolAddress((void**)&Pq, g_P);
    float* Hr = Hq + (size_t)RQ * DD;
    float* Pr = Pq + (size_t)RQ * DD;

    dim3 gridProj(RQ / 128, DD / 128);
    proj_gemm<<<gridProj, 256>>>(sq, W1, b1, Hq, 1);
    proj_gemm<<<gridProj, 256>>>(sr, W1, b1, Hr, 1);
    proj_gemm<<<gridProj, 256>>>(Hq, W2, b2, Pq, 0);
    proj_gemm<<<gridProj, 256>>>(Hr, W2, b2, Pr, 0);

    rownorm_kernel<<<RTOT / 8, 256>>>();
    prep_kernel<<<BB, 512>>>(mq, mr);

    cross_kernel<<<dim3(4, 4, BB), 256>>>(out_C);
    ebuild_kernel<<<RQ / 8, 256>>>(out_C);

    for (int i = 0; i < NI; i++) {
        row_pass<<<BB * 8, 256>>>();
        col_pass<<<BB * 8, 256>>>();
    }

    mi_first<<<BB * 8, 256>>>(out_T);
    mi_fused<<<BB * 8, 256>>>(out_T, 0, 1);
    mi_fused<<<BB * 8, 256>>>(out_T, 1, 2);
    mi_last<<<BB * 8, 256>>>(out_T, out_C, 2);

    finalize_kernel<<<1, 64>>>(out_sim, out_c);
}

// round 5
// speedup vs baseline: 1.3373x; 1.0698x over previous
#include <cuda_runtime.h>
#include <cuda_bf16.h>
#include <math.h>
#include <stdint.h>

// Problem constants
#define BB 64
#define KK 512
#define MM 512
#define DD 256
#define NI 15
#define MI 3
#define RQ (BB*KK)              // 32768
#define RTOT (2*RQ)             // 65536
#define PLANE ((size_t)KK*MM)
#define TOTE ((size_t)BB*PLANE) // 16777216

// ---------------- device scratch (static; no allocation) ----------------
__device__ float g_Xt[(size_t)DD*RTOT];   // k-major inputs
__device__ float g_Ht[(size_t)DD*RTOT];   // k-major hidden
__device__ float g_Pt[(size_t)DD*RTOT];   // k-major projections
__device__ float g_W1t[(size_t)DD*DD];
__device__ float g_W2t[(size_t)DD*DD];
__device__ float g_E[TOTE];
__device__ float g_q2[RQ], g_r2[RQ];
__device__ float g_logmu[RQ], g_lognu[RQ], g_rowRef[RQ];
__device__ float g_la[RQ], g_lb[RQ];
__device__ float g_colsum[3*RQ];
__device__ float g_cvec[BB];

// ---------------- fast exp on FMA pipe ----------------
__device__ __forceinline__ float fexp(float x) {
    x = fminf(fmaxf(x, -87.0f), 88.0f);
    const float L2E    = 1.4426950408889634f;
    const float L2E_LO = 1.9259629911e-8f;
    float t  = fmaf(x, L2E, 12582912.0f);
    float kf = t - 12582912.0f;
    float r  = fmaf(x, L2E, -kf);
    r = fmaf(x, L2E_LO, r);
    float p = 1.5403530e-4f;
    p = fmaf(p, r, 1.33335581e-3f);
    p = fmaf(p, r, 9.61812911e-3f);
    p = fmaf(p, r, 5.55041087e-2f);
    p = fmaf(p, r, 2.40226507e-1f);
    p = fmaf(p, r, 6.93147182e-1f);
    p = fmaf(p, r, 1.0f);
    int ei = (int)kf;
    float s = __int_as_float((ei + 127) << 23);
    return p * s;
}

// ---------------- small PTX helpers ----------------
__device__ __forceinline__ uint32_t smem_u32(const void* p) {
    return (uint32_t)__cvta_generic_to_shared(p);
}
__device__ __forceinline__ void cpasync16(uint32_t s, const void* g) {
    asm volatile("cp.async.cg.shared.global [%0], [%1], 16;" :: "r"(s), "l"(g));
}
#define CP_COMMIT asm volatile("cp.async.commit_group;" ::: "memory")
#define CP_WAIT0  asm volatile("cp.async.wait_group 0;" ::: "memory")

// ---------------- transpose: out[c][coloff + r] = in[r][c], cols = 256 ----------------
__global__ void __launch_bounds__(256) transpose_k(const float* __restrict__ in,
                                                   float* __restrict__ out,
                                                   int ldout, int coloff) {
    __shared__ float tile[32][33];
    int r0 = blockIdx.x * 32, c0 = blockIdx.y * 32;
    int tx = threadIdx.x & 31, tg = threadIdx.x >> 5;
#pragma unroll
    for (int i = tg; i < 32; i += 8)
        tile[i][tx] = in[(size_t)(r0 + i) * 256 + c0 + tx];
    __syncthreads();
#pragma unroll
    for (int i = tg; i < 32; i += 8)
        out[(size_t)(c0 + i) * ldout + coloff + r0 + tx] = tile[tx][i];
}

// ============================================================================
// k-major GEMM: D[m][n] = sum_k A[k][acol+m] * B[k][bcol+n], 128x128 tile,
// BK=8, cp.async double-buffered, 256 threads, 8x8 per-thread.
// mode 0: out = relu(D + bias[m]) -> out[(acol+m)*RTOT + bcol+n]
// mode 1: out = D + bias[m], plus row-norm atomics into g_q2/g_r2
// mode 2: cross: C = sqrt(max(q2+r2-2D,1e-6)) -> C[(acol+m)*512 + y*128+n]
// ============================================================================
__global__ void __launch_bounds__(256, 2) gemm_t(
    const float* __restrict__ A, int lda,
    const float* __restrict__ B, int ldb,
    const float* __restrict__ bias,
    float* __restrict__ out, int mode)
{
    __shared__ float As[2][8][128];
    __shared__ float Bs[2][8][128];
    __shared__ float s_aux[128];
    __shared__ float s_norm[128];

    int acol, bcol;
    if (mode < 2) { acol = blockIdx.x * 128; bcol = blockIdx.y * 128; }
    else {
        acol = blockIdx.z * 512 + blockIdx.x * 128;
        bcol = RQ + blockIdx.z * 512 + blockIdx.y * 128;
    }
    int t = threadIdx.x;
    int tx = t & 15, ty = t >> 4;

    if (t < 128) {
        s_aux[t] = (mode < 2) ? bias[acol + t] : g_r2[bcol - RQ + t];
        if (mode == 1) s_norm[t] = 0.f;
    }

    int krow = t >> 5, seg = t & 31;
    const float* Ag = A + (size_t)krow * lda + acol + seg * 4;
    const float* Bg = B + (size_t)krow * ldb + bcol + seg * 4;
    uint32_t sA = smem_u32(&As[0][krow][seg * 4]);
    uint32_t sB = smem_u32(&Bs[0][krow][seg * 4]);

    float acc[8][8];
#pragma unroll
    for (int i = 0; i < 8; i++)
#pragma unroll
        for (int j = 0; j < 8; j++) acc[i][j] = 0.f;

    cpasync16(sA, Ag);
    cpasync16(sB, Bg);
    CP_COMMIT;

#pragma unroll 1
    for (int kb = 0; kb < 32; kb++) {
        CP_WAIT0;
        __syncthreads();
        if (kb < 31) {
            int nb = (kb + 1) & 1;
            cpasync16(sA + nb * 4096, Ag + (size_t)(kb + 1) * 8 * lda);
            cpasync16(sB + nb * 4096, Bg + (size_t)(kb + 1) * 8 * ldb);
            CP_COMMIT;
        }
        int buf = kb & 1;
#pragma unroll
        for (int kk = 0; kk < 8; kk++) {
            float a[8], b[8];
            *(float4*)&a[0] = *(const float4*)&As[buf][kk][ty * 4];
            *(float4*)&a[4] = *(const float4*)&As[buf][kk][ty * 4 + 64];
            *(float4*)&b[0] = *(const float4*)&Bs[buf][kk][tx * 4];
            *(float4*)&b[4] = *(const float4*)&Bs[buf][kk][tx * 4 + 64];
#pragma unroll
            for (int i = 0; i < 8; i++)
#pragma unroll
                for (int j = 0; j < 8; j++) acc[i][j] = fmaf(a[i], b[j], acc[i][j]);
        }
        __syncthreads();
    }

    if (mode < 2) {
        float nrm[8];
#pragma unroll
        for (int j = 0; j < 8; j++) nrm[j] = 0.f;
#pragma unroll
        for (int i = 0; i < 8; i++) {
            int ml = ty * 4 + (i & 3) + ((i >= 4) ? 64 : 0);
            float bsv = s_aux[ml];
            float4 o0, o1;
            o0.x = acc[i][0] + bsv; o0.y = acc[i][1] + bsv;
            o0.z = acc[i][2] + bsv; o0.w = acc[i][3] + bsv;
            o1.x = acc[i][4] + bsv; o1.y = acc[i][5] + bsv;
            o1.z = acc[i][6] + bsv; o1.w = acc[i][7] + bsv;
            if (mode == 0) {
                o0.x = fmaxf(o0.x, 0.f); o0.y = fmaxf(o0.y, 0.f);
                o0.z = fmaxf(o0.z, 0.f); o0.w = fmaxf(o0.w, 0.f);
                o1.x = fmaxf(o1.x, 0.f); o1.y = fmaxf(o1.y, 0.f);
                o1.z = fmaxf(o1.z, 0.f); o1.w = fmaxf(o1.w, 0.f);
            } else {
                nrm[0] += o0.x * o0.x; nrm[1] += o0.y * o0.y;
                nrm[2] += o0.z * o0.z; nrm[3] += o0.w * o0.w;
                nrm[4] += o1.x * o1.x; nrm[5] += o1.y * o1.y;
                nrm[6] += o1.z * o1.z; nrm[7] += o1.w * o1.w;
            }
            size_t ob = (size_t)(acol + ml) * RTOT + bcol;
            *(float4*)&out[ob + tx * 4]      = o0;
            *(float4*)&out[ob + tx * 4 + 64] = o1;
        }
        if (mode == 1) {
#pragma unroll
            for (int j = 0; j < 8; j++) {
                int nl = tx * 4 + (j & 3) + ((j >= 4) ? 64 : 0);
                atomicAdd(&s_norm[nl], nrm[j]);
            }
            __syncthreads();
            if (t < 128) {
                int gc = bcol + t;
                if (gc < RQ) atomicAdd(&g_q2[gc], s_norm[t]);
                else         atomicAdd(&g_r2[gc - RQ], s_norm[t]);
            }
        }
    } else {
#pragma unroll
        for (int i = 0; i < 8; i++) {
            int ml = ty * 4 + (i & 3) + ((i >= 4) ? 64 : 0);
            float q2v = g_q2[acol + ml];
            float4 o0, o1;
            o0.x = sqrtf(fmaxf(q2v + s_aux[tx * 4 + 0]  - 2.f * acc[i][0], 1e-6f));
            o0.y = sqrtf(fmaxf(q2v + s_aux[tx * 4 + 1]  - 2.f * acc[i][1], 1e-6f));
            o0.z = sqrtf(fmaxf(q2v + s_aux[tx * 4 + 2]  - 2.f * acc[i][2], 1e-6f));
            o0.w = sqrtf(fmaxf(q2v + s_aux[tx * 4 + 3]  - 2.f * acc[i][3], 1e-6f));
            o1.x = sqrtf(fmaxf(q2v + s_aux[tx * 4 + 64] - 2.f * acc[i][4], 1e-6f));
            o1.y = sqrtf(fmaxf(q2v + s_aux[tx * 4 + 65] - 2.f * acc[i][5], 1e-6f));
            o1.z = sqrtf(fmaxf(q2v + s_aux[tx * 4 + 66] - 2.f * acc[i][6], 1e-6f));
            o1.w = sqrtf(fmaxf(q2v + s_aux[tx * 4 + 67] - 2.f * acc[i][7], 1e-6f));
            size_t ob = (size_t)(acol + ml) * 512 + blockIdx.y * 128;
            *(float4*)&out[ob + tx * 4]      = o0;
            *(float4*)&out[ob + tx * 4 + 64] = o1;
        }
    }
}

// ---------------- prep: logmu/lognu, zero buffers ----------------
__global__ void __launch_bounds__(512) prep_kernel(const float* __restrict__ mq,
                                                   const float* __restrict__ mr) {
    __shared__ float red[512];
    int b = blockIdx.x, t = threadIdx.x;
    float vq = mq[b * 512 + t];
    red[t] = vq; __syncthreads();
    for (int s = 256; s; s >>= 1) { if (t < s) red[t] += red[t + s]; __syncthreads(); }
    float smq = red[0]; __syncthreads();
    g_logmu[b * 512 + t] = logf(fmaxf(vq / (smq + 1e-8f), 1e-8f));

    float vr = mr[b * 512 + t];
    red[t] = vr; __syncthreads();
    for (int s = 256; s; s >>= 1) { if (t < s) red[t] += red[t + s]; __syncthreads(); }
    float smr = red[0]; __syncthreads();
    g_lognu[b * 512 + t] = logf(fmaxf(vr / (smr + 1e-8f), 1e-8f));

    g_q2[b * 512 + t] = 0.f;
    g_r2[b * 512 + t] = 0.f;
    g_colsum[0 * RQ + b * 512 + t] = 0.f;
    g_colsum[1 * RQ + b * 512 + t] = 0.f;
    g_colsum[2 * RQ + b * 512 + t] = 0.f;
    if (t == 0) g_cvec[b] = 0.f;
}

// ---------------- build E = exp(-20C + lognu - rowmax) ----------------
__global__ void __launch_bounds__(256) ebuild_kernel(const float* __restrict__ C) {
    int wid = threadIdx.x >> 5, lane = threadIdx.x & 31;
    int gid = blockIdx.x * 8 + wid;
    int b = gid >> 9;
    size_t base = (size_t)gid * 512;
    const float4* Crow = (const float4*)(C + base);
    const float4* Nu   = (const float4*)(g_lognu + (size_t)b * 512);
    float4 v4[4];
    float mx = -1e30f;
#pragma unroll
    for (int c = 0; c < 4; c++) {
        float4 cc = Crow[lane + 32 * c];
        float4 nu = Nu[lane + 32 * c];
        float4 v;
        v.x = fmaf(cc.x, -20.f, nu.x);
        v.y = fmaf(cc.y, -20.f, nu.y);
        v.z = fmaf(cc.z, -20.f, nu.z);
        v.w = fmaf(cc.w, -20.f, nu.w);
        v4[c] = v;
        mx = fmaxf(mx, fmaxf(fmaxf(v.x, v.y), fmaxf(v.z, v.w)));
    }
#pragma unroll
    for (int o = 16; o; o >>= 1) mx = fmaxf(mx, __shfl_xor_sync(~0u, mx, o));
    float4* Erow = (float4*)(g_E + base);
#pragma unroll
    for (int c = 0; c < 4; c++) {
        float4 e;
        e.x = fexp(v4[c].x - mx); e.y = fexp(v4[c].y - mx);
        e.z = fexp(v4[c].z - mx); e.w = fexp(v4[c].w - mx);
        Erow[lane + 32 * c] = e;
    }
    if (lane == 0) g_rowRef[gid] = mx;
}

// ============================================================================
// Fused Sinkhorn: ONE launch, one 1024-thread CTA per batch, 15 iterations.
// No clusters, no DSMEM — everything block-local.
// ============================================================================
__global__ void __launch_bounds__(1024, 1) sinkhorn_fused_b() {
    __shared__ __align__(16) float s_vb[512];
    __shared__ float s_wa[512];
    __shared__ float s_g[512];
    __shared__ float s_lb[512];
    __shared__ float s_rc[512];
    __shared__ float s_red[1024];

    int b = blockIdx.x;
    int t = threadIdx.x;
    int wid = t >> 5, lane = t & 31;
    const float* Eb = g_E + (size_t)b * 512 * 512;

    if (t < 512) {
        s_rc[t] = g_logmu[b * 512 + t] + g_rowRef[b * 512 + t];
        s_lb[t] = 0.f;
    }
    __syncthreads();

    for (int it = 0; it < NI; it++) {
        // sb = max over s_lb
        s_red[t] = (t < 512) ? s_lb[t] : -1e30f;
        __syncthreads();
        for (int s = 512; s; s >>= 1) {
            if (t < s) s_red[t] = fmaxf(s_red[t], s_red[t + s]);
            __syncthreads();
        }
        float sb = s_red[0];
        __syncthreads();
        if (t < 512) s_vb[t] = fexp(s_lb[t] - sb);
        __syncthreads();

        // row phase: 32 warps x 16 rows, warp-per-row dot product
#pragma unroll 1
        for (int rr = wid; rr < 512; rr += 32) {
            const float4* Er = (const float4*)(Eb + (size_t)rr * 512);
            const float4* V  = (const float4*)s_vb;
            float acc = 0.f;
#pragma unroll
            for (int c = 0; c < 4; c++) {
                float4 e = Er[lane + 32 * c];
                float4 v = V[lane + 32 * c];
                acc += e.x * v.x + e.y * v.y + e.z * v.z + e.w * v.w;
            }
#pragma unroll
            for (int o = 16; o; o >>= 1) acc += __shfl_xor_sync(~0u, acc, o);
            if (lane == 0) s_g[rr] = -(sb + logf(fmaxf(acc, 1e-35f)));
        }
        __syncthreads();

        // sa = max over s_g
        s_red[t] = (t < 512) ? s_g[t] : -1e30f;
        __syncthreads();
        for (int s = 512; s; s >>= 1) {
            if (t < s) s_red[t] = fmaxf(s_red[t], s_red[t + s]);
            __syncthreads();
        }
        float sa = s_red[0];
        __syncthreads();
        if (t < 512) s_wa[t] = fexp(s_g[t] - sa);
        __syncthreads();

        // col phase: thread t -> col t&511, rows half*256..+255
        {
            int col = t & 511, half = t >> 9;
            const float* Ecol = Eb + (size_t)half * 256 * 512 + col;
            const float* W = s_wa + half * 256;
            float a0 = 0.f, a1 = 0.f, a2 = 0.f, a3 = 0.f;
#pragma unroll 4
            for (int r = 0; r < 256; r += 4) {
                a0 = fmaf(Ecol[(size_t)(r + 0) * 512], W[r + 0], a0);
                a1 = fmaf(Ecol[(size_t)(r + 1) * 512], W[r + 1], a1);
                a2 = fmaf(Ecol[(size_t)(r + 2) * 512], W[r + 2], a2);
                a3 = fmaf(Ecol[(size_t)(r + 3) * 512], W[r + 3], a3);
            }
            s_red[t] = (a0 + a1) + (a2 + a3);
        }
        __syncthreads();
        if (t < 512) s_lb[t] = -(sa + logf(fmaxf(s_red[t] + s_red[t + 512], 1e-35f)));
        __syncthreads();
    }

    if (t < 512) {
        g_la[b * 512 + t] = s_g[t] - s_rc[t];
        g_lb[b * 512 + t] = s_lb[t];
    }
}

// ---------------- MI it=0 ----------------
__global__ void __launch_bounds__(256) mi_first(float* __restrict__ T) {
    __shared__ float rb[512];
    __shared__ float cs[512];
    int b = blockIdx.x >> 3, r0 = (blockIdx.x & 7) * 64;
    int t = threadIdx.x;
    for (int i = t; i < 512; i += 256) {
        rb[i] = fexp(g_lb[b * 512 + i]);
        cs[i] = 0.f;
    }
    __syncthreads();
    int wid = t >> 5, lane = t & 31;
    float4 csum[4];
#pragma unroll
    for (int c = 0; c < 4; c++) csum[c] = make_float4(0.f, 0.f, 0.f, 0.f);
    for (int rr = wid; rr < 64; rr += 8) {
        int k = r0 + rr;
        size_t base = ((size_t)b * 512 + k) * 512;
        float ra = fexp(g_logmu[b * 512 + k] + g_rowRef[b * 512 + k] + g_la[b * 512 + k]);
        float4 tv[4];
        float rs = 0.f;
#pragma unroll
        for (int c = 0; c < 4; c++) {
            int off = lane + 32 * c;
            float4 e  = ((const float4*)(g_E + base))[off];
            float4 r4 = ((const float4*)rb)[off];
            float4 x;
            x.x = e.x * ra * r4.x; x.y = e.y * ra * r4.y;
            x.z = e.z * ra * r4.z; x.w = e.w * ra * r4.w;
            x.x *= x.x; x.y *= x.y; x.z *= x.z; x.w *= x.w;
            tv[c] = x;
            rs += x.x + x.y + x.z + x.w;
        }
#pragma unroll
        for (int o = 16; o; o >>= 1) rs += __shfl_xor_sync(~0u, rs, o);
        float inv = 1.0f / (rs + 1e-8f);
#pragma unroll
        for (int c = 0; c < 4; c++) {
            int off = lane + 32 * c;
            float4 o4;
            o4.x = tv[c].x * inv; o4.y = tv[c].y * inv;
            o4.z = tv[c].z * inv; o4.w = tv[c].w * inv;
            ((float4*)(T + base))[off] = o4;
            csum[c].x += o4.x; csum[c].y += o4.y;
            csum[c].z += o4.z; csum[c].w += o4.w;
        }
    }
#pragma unroll
    for (int c = 0; c < 4; c++) {
        int m = (lane + 32 * c) * 4;
        atomicAdd(&cs[m + 0], csum[c].x); atomicAdd(&cs[m + 1], csum[c].y);
        atomicAdd(&cs[m + 2], csum[c].z); atomicAdd(&cs[m + 3], csum[c].w);
    }
    __syncthreads();
    for (int i = t; i < 512; i += 256)
        atomicAdd(&g_colsum[b * 512 + i], cs[i]);
}

// ---------------- MI fused ----------------
__global__ void __launch_bounds__(256) mi_fused(float* __restrict__ T, int prev, int it) {
    __shared__ float inv[512];
    __shared__ float cs[512];
    int b = blockIdx.x >> 3, r0 = (blockIdx.x & 7) * 64;
    int t = threadIdx.x;
    for (int i = t; i < 512; i += 256) {
        inv[i] = 1.0f / (g_colsum[(size_t)prev * RQ + b * 512 + i] + 1e-8f);
        cs[i] = 0.f;
    }
    __syncthreads();
    int wid = t >> 5, lane = t & 31;
    float4 csum[4];
#pragma unroll
    for (int c = 0; c < 4; c++) csum[c] = make_float4(0.f, 0.f, 0.f, 0.f);
    for (int rr = wid; rr < 64; rr += 8) {
        int k = r0 + rr;
        size_t base = ((size_t)b * 512 + k) * 512;
        float4 tv[4];
        float rs = 0.f;
#pragma unroll
        for (int c = 0; c < 4; c++) {
            int off = lane + 32 * c;
            float4 x  = ((const float4*)(T + base))[off];
            float4 iv = ((const float4*)inv)[off];
            x.x *= iv.x; x.y *= iv.y; x.z *= iv.z; x.w *= iv.w;
            x.x *= x.x; x.y *= x.y; x.z *= x.z; x.w *= x.w;
            tv[c] = x;
            rs += x.x + x.y + x.z + x.w;
        }
#pragma unroll
        for (int o = 16; o; o >>= 1) rs += __shfl_xor_sync(~0u, rs, o);
        float rinv = 1.0f / (rs + 1e-8f);
#pragma unroll
        for (int c = 0; c < 4; c++) {
            int off = lane + 32 * c;
            float4 o4;
            o4.x = tv[c].x * rinv; o4.y = tv[c].y * rinv;
            o4.z = tv[c].z * rinv; o4.w = tv[c].w * rinv;
            ((float4*)(T + base))[off] = o4;
            csum[c].x += o4.x; csum[c].y += o4.y;
            csum[c].z += o4.z; csum[c].w += o4.w;
        }
    }
#pragma unroll
    for (int c = 0; c < 4; c++) {
        int m = (lane + 32 * c) * 4;
        atomicAdd(&cs[m + 0], csum[c].x); atomicAdd(&cs[m + 1], csum[c].y);
        atomicAdd(&cs[m + 2], csum[c].z); atomicAdd(&cs[m + 3], csum[c].w);
    }
    __syncthreads();
    for (int i = t; i < 512; i += 256)
        atomicAdd(&g_colsum[(size_t)it * RQ + b * 512 + i], cs[i]);
}

// ---------------- MI last ----------------
__global__ void __launch_bounds__(256) mi_last(float* __restrict__ T,
                                               const float* __restrict__ C,
                                               int last) {
    __shared__ float inv[512];
    __shared__ float red[8];
    int b = blockIdx.x >> 3, r0 = (blockIdx.x & 7) * 64;
    int t = threadIdx.x;
    for (int i = t; i < 512; i += 256)
        inv[i] = 1.0f / (g_colsum[(size_t)last * RQ + b * 512 + i] + 1e-8f);
    __syncthreads();
    int wid = t >> 5, lane = t & 31;
    float cacc = 0.f;
    for (int rr = wid; rr < 64; rr += 8) {
        int k = r0 + rr;
        size_t base = ((size_t)b * 512 + k) * 512;
#pragma unroll
        for (int c = 0; c < 4; c++) {
            int off = lane + 32 * c;
            float4 x  = ((const float4*)(T + base))[off];
            float4 iv = ((const float4*)inv)[off];
            x.x *= iv.x; x.y *= iv.y; x.z *= iv.z; x.w *= iv.w;
            ((float4*)(T + base))[off] = x;
            float4 cc = ((const float4*)(C + base))[off];
            cacc += x.x * cc.x + x.y * cc.y + x.z * cc.z + x.w * cc.w;
        }
    }
#pragma unroll
    for (int o = 16; o; o >>= 1) cacc += __shfl_xor_sync(~0u, cacc, o);
    if (lane == 0) red[wid] = cacc;
    __syncthreads();
    if (t == 0) {
        float s = 0.f;
#pragma unroll
        for (int w = 0; w < 8; w++) s += red[w];
        atomicAdd(&g_cvec[b], s);
    }
}

// ---------------- finalize ----------------
__global__ void finalize_kernel(float* __restrict__ sim, float* __restrict__ outc) {
    int b = threadIdx.x;
    if (b < BB) {
        float c = g_cvec[b];
        outc[b] = c;
        sim[b] = 1.0f / (1.0f + expf(c));
    }
}

// ---------------- launch ----------------
extern "C" void kernel_launch(void* const* d_in, const int* in_sizes, int n_in,
                              void* d_out, int out_size) {
    const float* sq = (const float*)d_in[0];
    const float* sr = (const float*)d_in[1];
    const float* mq = (const float*)d_in[2];
    const float* mr = (const float*)d_in[3];
    const float* W1 = (const float*)d_in[4];
    const float* b1 = (const float*)d_in[5];
    const float* W2 = (const float*)d_in[6];
    const float* b2 = (const float*)d_in[7];

    float* out = (float*)d_out;
    float* out_sim = out;
    float* out_T   = out + BB;
    float* out_C   = out + BB + TOTE;
    float* out_c   = out + BB + 2 * TOTE;

    float* Xt;  cudaGetSymbolAddress((void**)&Xt, g_Xt);
    float* Ht;  cudaGetSymbolAddress((void**)&Ht, g_Ht);
    float* Pt;  cudaGetSymbolAddress((void**)&Pt, g_Pt);
    float* W1t; cudaGetSymbolAddress((void**)&W1t, g_W1t);
    float* W2t; cudaGetSymbolAddress((void**)&W2t, g_W2t);

    prep_kernel<<<BB, 512>>>(mq, mr);

    // transposes to k-major
    transpose_k<<<dim3(RQ / 32, 8), 256>>>(sq, Xt, RTOT, 0);
    transpose_k<<<dim3(RQ / 32, 8), 256>>>(sr, Xt, RTOT, RQ);
    transpose_k<<<dim3(8, 8), 256>>>(W1, W1t, 256, 0);
    transpose_k<<<dim3(8, 8), 256>>>(W2, W2t, 256, 0);

    // layer 1: Ht = relu(W1 @ Xt + b1)  [feature][row]
    gemm_t<<<dim3(2, RTOT / 128), 256>>>(W1t, 256, Xt, RTOT, b1, Ht, 0);
    // layer 2: Pt = W2 @ Ht + b2, with row-norm atomics
    gemm_t<<<dim3(2, RTOT / 128), 256>>>(W2t, 256, Ht, RTOT, b2, Pt, 1);
    // cross distances
    gemm_t<<<dim3(4, 4, BB), 256>>>(Pt, RTOT, Pt, RTOT, nullptr, out_C, 2);

    ebuild_kernel<<<RQ / 8, 256>>>(out_C);

    sinkhorn_fused_b<<<BB, 1024>>>();

    mi_first<<<BB * 8, 256>>>(out_T);
    mi_fused<<<BB * 8, 256>>>(out_T, 0, 1);
    mi_fused<<<BB * 8, 256>>>(out_T, 1, 2);
    mi_last<<<BB * 8, 256>>>(out_T, out_C, 2);

    finalize_kernel<<<1, 64>>>(out_sim, out_c);
}

// round 6
// speedup vs baseline: 1.3985x; 1.0458x over previous
#include <cuda_runtime.h>
#include <cuda_bf16.h>
#include <math.h>
#include <stdint.h>

// Problem constants
#define BB 64
#define KK 512
#define MM 512
#define DD 256
#define NI 15
#define MI 3
#define RQ (BB*KK)              // 32768
#define RTOT (2*RQ)             // 65536
#define PLANE ((size_t)KK*MM)
#define TOTE ((size_t)BB*PLANE) // 16777216

// ---------------- device scratch (static; no allocation) ----------------
__device__ float g_Xt[(size_t)DD*RTOT];   // k-major inputs
__device__ float g_Ht[(size_t)DD*RTOT];   // k-major hidden
__device__ float g_Pt[(size_t)DD*RTOT];   // k-major projections
__device__ float g_W1t[(size_t)DD*DD];
__device__ float g_W2t[(size_t)DD*DD];
__device__ float g_E[TOTE];
__device__ float g_q2[RQ], g_r2[RQ];
__device__ float g_logmu[RQ], g_lognu[RQ], g_rowRef[RQ];
__device__ float g_la[RQ], g_lb[RQ];
__device__ float g_colsum[3*RQ];
__device__ float g_cvec[BB];

// ---------------- fast exp on FMA pipe ----------------
__device__ __forceinline__ float fexp(float x) {
    x = fminf(fmaxf(x, -87.0f), 88.0f);
    const float L2E    = 1.4426950408889634f;
    const float L2E_LO = 1.9259629911e-8f;
    float t  = fmaf(x, L2E, 12582912.0f);
    float kf = t - 12582912.0f;
    float r  = fmaf(x, L2E, -kf);
    r = fmaf(x, L2E_LO, r);
    float p = 1.5403530e-4f;
    p = fmaf(p, r, 1.33335581e-3f);
    p = fmaf(p, r, 9.61812911e-3f);
    p = fmaf(p, r, 5.55041087e-2f);
    p = fmaf(p, r, 2.40226507e-1f);
    p = fmaf(p, r, 6.93147182e-1f);
    p = fmaf(p, r, 1.0f);
    int ei = (int)kf;
    float s = __int_as_float((ei + 127) << 23);
    return p * s;
}

// ---------------- small PTX helpers ----------------
__device__ __forceinline__ uint32_t smem_u32(const void* p) {
    return (uint32_t)__cvta_generic_to_shared(p);
}
__device__ __forceinline__ void cpasync16(uint32_t s, const void* g) {
    asm volatile("cp.async.cg.shared.global [%0], [%1], 16;" :: "r"(s), "l"(g));
}
#define CP_COMMIT asm volatile("cp.async.commit_group;" ::: "memory")
#define CP_WAIT0  asm volatile("cp.async.wait_group 0;" ::: "memory")
#define CP_WAIT1  asm volatile("cp.async.wait_group 1;" ::: "memory")

__device__ __forceinline__ float dsmem_ld_f(uint32_t saddr, uint32_t rank) {
    uint32_t ra; float v;
    asm volatile("mapa.shared::cluster.u32 %0, %1, %2;" : "=r"(ra) : "r"(saddr), "r"(rank));
    asm volatile("ld.shared::cluster.f32 %0, [%1];" : "=f"(v) : "r"(ra));
    return v;
}
__device__ __forceinline__ void cluster_sync_() {
    asm volatile("barrier.cluster.arrive.aligned;" ::: "memory");
    asm volatile("barrier.cluster.wait.aligned;" ::: "memory");
}

// ---------------- transpose: out[c][coloff + r] = in[r][c], cols = 256 ----------------
__global__ void __launch_bounds__(256) transpose_k(const float* __restrict__ in,
                                                   float* __restrict__ out,
                                                   int ldout, int coloff) {
    __shared__ float tile[32][33];
    int r0 = blockIdx.x * 32, c0 = blockIdx.y * 32;
    int tx = threadIdx.x & 31, tg = threadIdx.x >> 5;
#pragma unroll
    for (int i = tg; i < 32; i += 8)
        tile[i][tx] = in[(size_t)(r0 + i) * 256 + c0 + tx];
    __syncthreads();
#pragma unroll
    for (int i = tg; i < 32; i += 8)
        out[(size_t)(c0 + i) * ldout + coloff + r0 + tx] = tile[tx][i];
}

// ============================================================================
// k-major GEMM: D[m][n] = sum_k A[k][acol+m] * B[k][bcol+n], 128x128 tile,
// BK=8, 3-stage cp.async pipeline, ONE sync per k-iter, 256 threads, 8x8/thread
// mode 0: out = relu(D + bias[m]) -> out[(acol+m)*RTOT + bcol+n]
// mode 1: out = D + bias[m], plus row-norm atomics into g_q2/g_r2
// mode 2: cross: C = sqrt(max(q2+r2-2D,1e-6)) -> C[(acol+m)*512 + y*128+n]
// ============================================================================
__global__ void __launch_bounds__(256, 2) gemm_t(
    const float* __restrict__ A, int lda,
    const float* __restrict__ B, int ldb,
    const float* __restrict__ bias,
    float* __restrict__ out, int mode)
{
    __shared__ float As[3][8][128];
    __shared__ float Bs[3][8][128];
    __shared__ float s_aux[128];
    __shared__ float s_norm[128];

    int acol, bcol;
    if (mode < 2) { acol = blockIdx.x * 128; bcol = blockIdx.y * 128; }
    else {
        acol = blockIdx.z * 512 + blockIdx.x * 128;
        bcol = RQ + blockIdx.z * 512 + blockIdx.y * 128;
    }
    int t = threadIdx.x;
    int tx = t & 15, ty = t >> 4;

    if (t < 128) {
        s_aux[t] = (mode < 2) ? bias[acol + t] : g_r2[bcol - RQ + t];
        if (mode == 1) s_norm[t] = 0.f;
    }

    int krow = t >> 5, seg = t & 31;
    const float* Ag = A + (size_t)krow * lda + acol + seg * 4;
    const float* Bg = B + (size_t)krow * ldb + bcol + seg * 4;
    uint32_t sA = smem_u32(&As[0][krow][seg * 4]);
    uint32_t sB = smem_u32(&Bs[0][krow][seg * 4]);

    float acc[8][8];
#pragma unroll
    for (int i = 0; i < 8; i++)
#pragma unroll
        for (int j = 0; j < 8; j++) acc[i][j] = 0.f;

    // prologue: stages 0, 1
    cpasync16(sA, Ag);
    cpasync16(sB, Bg);
    CP_COMMIT;
    cpasync16(sA + 4096, Ag + (size_t)8 * lda);
    cpasync16(sB + 4096, Bg + (size_t)8 * ldb);
    CP_COMMIT;

#pragma unroll 1
    for (int kb = 0; kb < 32; kb++) {
        if (kb < 31) { CP_WAIT1; } else { CP_WAIT0; }
        __syncthreads();
        if (kb < 30) {
            int nb = (kb + 2) % 3;
            cpasync16(sA + nb * 4096, Ag + (size_t)(kb + 2) * 8 * lda);
            cpasync16(sB + nb * 4096, Bg + (size_t)(kb + 2) * 8 * ldb);
            CP_COMMIT;
        }
        int buf = kb % 3;
#pragma unroll
        for (int kk = 0; kk < 8; kk++) {
            float a[8], b[8];
            *(float4*)&a[0] = *(const float4*)&As[buf][kk][ty * 4];
            *(float4*)&a[4] = *(const float4*)&As[buf][kk][ty * 4 + 64];
            *(float4*)&b[0] = *(const float4*)&Bs[buf][kk][tx * 4];
            *(float4*)&b[4] = *(const float4*)&Bs[buf][kk][tx * 4 + 64];
#pragma unroll
            for (int i = 0; i < 8; i++)
#pragma unroll
                for (int j = 0; j < 8; j++) acc[i][j] = fmaf(a[i], b[j], acc[i][j]);
        }
    }
    __syncthreads();

    if (mode < 2) {
        float nrm[8];
#pragma unroll
        for (int j = 0; j < 8; j++) nrm[j] = 0.f;
#pragma unroll
        for (int i = 0; i < 8; i++) {
            int ml = ty * 4 + (i & 3) + ((i >= 4) ? 64 : 0);
            float bsv = s_aux[ml];
            float4 o0, o1;
            o0.x = acc[i][0] + bsv; o0.y = acc[i][1] + bsv;
            o0.z = acc[i][2] + bsv; o0.w = acc[i][3] + bsv;
            o1.x = acc[i][4] + bsv; o1.y = acc[i][5] + bsv;
            o1.z = acc[i][6] + bsv; o1.w = acc[i][7] + bsv;
            if (mode == 0) {
                o0.x = fmaxf(o0.x, 0.f); o0.y = fmaxf(o0.y, 0.f);
                o0.z = fmaxf(o0.z, 0.f); o0.w = fmaxf(o0.w, 0.f);
                o1.x = fmaxf(o1.x, 0.f); o1.y = fmaxf(o1.y, 0.f);
                o1.z = fmaxf(o1.z, 0.f); o1.w = fmaxf(o1.w, 0.f);
            } else {
                nrm[0] += o0.x * o0.x; nrm[1] += o0.y * o0.y;
                nrm[2] += o0.z * o0.z; nrm[3] += o0.w * o0.w;
                nrm[4] += o1.x * o1.x; nrm[5] += o1.y * o1.y;
                nrm[6] += o1.z * o1.z; nrm[7] += o1.w * o1.w;
            }
            size_t ob = (size_t)(acol + ml) * RTOT + bcol;
            *(float4*)&out[ob + tx * 4]      = o0;
            *(float4*)&out[ob + tx * 4 + 64] = o1;
        }
        if (mode == 1) {
#pragma unroll
            for (int j = 0; j < 8; j++) {
                int nl = tx * 4 + (j & 3) + ((j >= 4) ? 64 : 0);
                atomicAdd(&s_norm[nl], nrm[j]);
            }
            __syncthreads();
            if (t < 128) {
                int gc = bcol + t;
                if (gc < RQ) atomicAdd(&g_q2[gc], s_norm[t]);
                else         atomicAdd(&g_r2[gc - RQ], s_norm[t]);
            }
        }
    } else {
#pragma unroll
        for (int i = 0; i < 8; i++) {
            int ml = ty * 4 + (i & 3) + ((i >= 4) ? 64 : 0);
            float q2v = g_q2[acol + ml];
            float4 o0, o1;
            o0.x = sqrtf(fmaxf(q2v + s_aux[tx * 4 + 0]  - 2.f * acc[i][0], 1e-6f));
            o0.y = sqrtf(fmaxf(q2v + s_aux[tx * 4 + 1]  - 2.f * acc[i][1], 1e-6f));
            o0.z = sqrtf(fmaxf(q2v + s_aux[tx * 4 + 2]  - 2.f * acc[i][2], 1e-6f));
            o0.w = sqrtf(fmaxf(q2v + s_aux[tx * 4 + 3]  - 2.f * acc[i][3], 1e-6f));
            o1.x = sqrtf(fmaxf(q2v + s_aux[tx * 4 + 64] - 2.f * acc[i][4], 1e-6f));
            o1.y = sqrtf(fmaxf(q2v + s_aux[tx * 4 + 65] - 2.f * acc[i][5], 1e-6f));
            o1.z = sqrtf(fmaxf(q2v + s_aux[tx * 4 + 66] - 2.f * acc[i][6], 1e-6f));
            o1.w = sqrtf(fmaxf(q2v + s_aux[tx * 4 + 67] - 2.f * acc[i][7], 1e-6f));
            size_t ob = (size_t)(acol + ml) * 512 + blockIdx.y * 128;
            *(float4*)&out[ob + tx * 4]      = o0;
            *(float4*)&out[ob + tx * 4 + 64] = o1;
        }
    }
}

// ---------------- prep: logmu/lognu, zero buffers ----------------
__global__ void __launch_bounds__(512) prep_kernel(const float* __restrict__ mq,
                                                   const float* __restrict__ mr) {
    __shared__ float red[512];
    int b = blockIdx.x, t = threadIdx.x;
    float vq = mq[b * 512 + t];
    red[t] = vq; __syncthreads();
    for (int s = 256; s; s >>= 1) { if (t < s) red[t] += red[t + s]; __syncthreads(); }
    float smq = red[0]; __syncthreads();
    g_logmu[b * 512 + t] = logf(fmaxf(vq / (smq + 1e-8f), 1e-8f));

    float vr = mr[b * 512 + t];
    red[t] = vr; __syncthreads();
    for (int s = 256; s; s >>= 1) { if (t < s) red[t] += red[t + s]; __syncthreads(); }
    float smr = red[0]; __syncthreads();
    g_lognu[b * 512 + t] = logf(fmaxf(vr / (smr + 1e-8f), 1e-8f));

    g_q2[b * 512 + t] = 0.f;
    g_r2[b * 512 + t] = 0.f;
    g_colsum[0 * RQ + b * 512 + t] = 0.f;
    g_colsum[1 * RQ + b * 512 + t] = 0.f;
    g_colsum[2 * RQ + b * 512 + t] = 0.f;
    if (t == 0) g_cvec[b] = 0.f;
}

// ---------------- build E = exp(-20C + lognu - rowmax) ----------------
__global__ void __launch_bounds__(256) ebuild_kernel(const float* __restrict__ C) {
    int wid = threadIdx.x >> 5, lane = threadIdx.x & 31;
    int gid = blockIdx.x * 8 + wid;
    int b = gid >> 9;
    size_t base = (size_t)gid * 512;
    const float4* Crow = (const float4*)(C + base);
    const float4* Nu   = (const float4*)(g_lognu + (size_t)b * 512);
    float4 v4[4];
    float mx = -1e30f;
#pragma unroll
    for (int c = 0; c < 4; c++) {
        float4 cc = Crow[lane + 32 * c];
        float4 nu = Nu[lane + 32 * c];
        float4 v;
        v.x = fmaf(cc.x, -20.f, nu.x);
        v.y = fmaf(cc.y, -20.f, nu.y);
        v.z = fmaf(cc.z, -20.f, nu.z);
        v.w = fmaf(cc.w, -20.f, nu.w);
        v4[c] = v;
        mx = fmaxf(mx, fmaxf(fmaxf(v.x, v.y), fmaxf(v.z, v.w)));
    }
#pragma unroll
    for (int o = 16; o; o >>= 1) mx = fmaxf(mx, __shfl_xor_sync(~0u, mx, o));
    float4* Erow = (float4*)(g_E + base);
#pragma unroll
    for (int c = 0; c < 4; c++) {
        float4 e;
        e.x = fexp(v4[c].x - mx); e.y = fexp(v4[c].y - mx);
        e.z = fexp(v4[c].z - mx); e.w = fexp(v4[c].w - mx);
        Erow[lane + 32 * c] = e;
    }
    if (lane == 0) g_rowRef[gid] = mx;
}

// ============================================================================
// Fused Sinkhorn: cluster of 4 CTAs per batch (each owns 128 rows), 256 thr.
// Protocol per iter: [row phase] -> csync(A: locmax published)
//                    [read locmax, wa, col partials] -> csync(B: partials pub)
//                    [read partials -> lb] -> csync(C: reads done, safe reuse)
// Final csync before exit so no CTA dies while peers read its SMEM.
// ============================================================================
__global__ void __launch_bounds__(256, 1) __cluster_dims__(4, 1, 1)
sinkhorn_cluster() {
    __shared__ __align__(16) float s_vb[512];
    __shared__ float s_partial[512];
    __shared__ float s_lb[512];
    __shared__ float s_g[128];
    __shared__ float s_rc[128];
    __shared__ float s_wa[128];
    __shared__ float s_red[256];
    __shared__ float s_locmax;

    int bat = blockIdx.x >> 2;
    int rank = blockIdx.x & 3;
    int t = threadIdx.x;
    int wid = t >> 5, lane = t & 31;
    int rowbase = bat * 512 + rank * 128;
    const float* Eb  = g_E + (size_t)rowbase * 512;              // own 128 rows
    const float* Ebt = g_E + (size_t)(bat * 512 + rank * 128) * 512; // same

    if (t < 128) s_rc[t] = g_logmu[rowbase + t] + g_rowRef[rowbase + t];
    s_lb[t] = 0.f; s_lb[t + 256] = 0.f;
    __syncthreads();

    for (int it = 0; it < NI; it++) {
        // sb = max over full lb (local copy)
        s_red[t] = fmaxf(s_lb[t], s_lb[t + 256]);
        __syncthreads();
        for (int s = 128; s; s >>= 1) { if (t < s) s_red[t] = fmaxf(s_red[t], s_red[t + s]); __syncthreads(); }
        float sb = s_red[0];
        __syncthreads();
        s_vb[t]       = fexp(s_lb[t] - sb);
        s_vb[t + 256] = fexp(s_lb[t + 256] - sb);
        __syncthreads();

        // row phase: 8 warps x 16 rows
#pragma unroll 1
        for (int rr = wid; rr < 128; rr += 8) {
            const float4* Er = (const float4*)(Eb + (size_t)rr * 512);
            const float4* V  = (const float4*)s_vb;
            float acc = 0.f;
#pragma unroll
            for (int c = 0; c < 4; c++) {
                float4 e = Er[lane + 32 * c];
                float4 v = V[lane + 32 * c];
                acc += e.x * v.x + e.y * v.y + e.z * v.z + e.w * v.w;
            }
#pragma unroll
            for (int o = 16; o; o >>= 1) acc += __shfl_xor_sync(~0u, acc, o);
            if (lane == 0) s_g[rr] = -(sb + logf(fmaxf(acc, 1e-35f)));
        }
        __syncthreads();

        // local max of g -> s_locmax
        s_red[t] = (t < 128) ? s_g[t] : -1e30f;
        __syncthreads();
        for (int s = 128; s; s >>= 1) { if (t < s) s_red[t] = fmaxf(s_red[t], s_red[t + s]); __syncthreads(); }
        if (t == 0) s_locmax = s_red[0];
        __syncthreads();
        cluster_sync_();   // (A) locmax published everywhere

        float sa = -1e30f;
        uint32_t lmaddr = smem_u32(&s_locmax);
#pragma unroll
        for (int r = 0; r < 4; r++) sa = fmaxf(sa, dsmem_ld_f(lmaddr, r));

        if (t < 128) s_wa[t] = fexp(s_g[t] - sa);
        __syncthreads();

        // col partials over own 128 rows; thread t -> cols t, t+256
        {
            const float* E0 = Ebt + t;
            const float* E1 = Ebt + t + 256;
            float a0 = 0.f, a1 = 0.f, b0 = 0.f, b1 = 0.f;
#pragma unroll 8
            for (int row = 0; row < 128; row += 2) {
                float w0 = s_wa[row], w1 = s_wa[row + 1];
                a0 = fmaf(E0[(size_t)row * 512],       w0, a0);
                a1 = fmaf(E0[(size_t)(row + 1) * 512], w1, a1);
                b0 = fmaf(E1[(size_t)row * 512],       w0, b0);
                b1 = fmaf(E1[(size_t)(row + 1) * 512], w1, b1);
            }
            s_partial[t]       = a0 + a1;
            s_partial[t + 256] = b0 + b1;
        }
        __syncthreads();
        cluster_sync_();   // (B) partials published everywhere

#pragma unroll
        for (int cg = 0; cg < 2; cg++) {
            int col = t + cg * 256;
            uint32_t pa = smem_u32(&s_partial[col]);
            float s = 0.f;
#pragma unroll
            for (int r = 0; r < 4; r++) s += dsmem_ld_f(pa, r);
            s_lb[col] = -(sa + logf(fmaxf(s, 1e-35f)));
        }
        __syncthreads();
        cluster_sync_();   // (C) all remote reads done; safe to overwrite next iter
    }

    // outputs (local data only)
    if (t < 128) g_la[rowbase + t] = s_g[t] - s_rc[t];
    if (rank == 0) {
        g_lb[bat * 512 + t]       = s_lb[t];
        g_lb[bat * 512 + 256 + t] = s_lb[t + 256];
    }
    cluster_sync_();       // no CTA exits while peers might touch its SMEM
}

// ---------------- MI it=0 ----------------
__global__ void __launch_bounds__(256) mi_first(float* __restrict__ T) {
    __shared__ float rb[512];
    __shared__ float cs[512];
    int b = blockIdx.x >> 3, r0 = (blockIdx.x & 7) * 64;
    int t = threadIdx.x;
    for (int i = t; i < 512; i += 256) {
        rb[i] = fexp(g_lb[b * 512 + i]);
        cs[i] = 0.f;
    }
    __syncthreads();
    int wid = t >> 5, lane = t & 31;
    float4 csum[4];
#pragma unroll
    for (int c = 0; c < 4; c++) csum[c] = make_float4(0.f, 0.f, 0.f, 0.f);
    for (int rr = wid; rr < 64; rr += 8) {
        int k = r0 + rr;
        size_t base = ((size_t)b * 512 + k) * 512;
        float ra = fexp(g_logmu[b * 512 + k] + g_rowRef[b * 512 + k] + g_la[b * 512 + k]);
        float4 tv[4];
        float rs = 0.f;
#pragma unroll
        for (int c = 0; c < 4; c++) {
            int off = lane + 32 * c;
            float4 e  = ((const float4*)(g_E + base))[off];
            float4 r4 = ((const float4*)rb)[off];
            float4 x;
            x.x = e.x * ra * r4.x; x.y = e.y * ra * r4.y;
            x.z = e.z * ra * r4.z; x.w = e.w * ra * r4.w;
            x.x *= x.x; x.y *= x.y; x.z *= x.z; x.w *= x.w;
            tv[c] = x;
            rs += x.x + x.y + x.z + x.w;
        }
#pragma unroll
        for (int o = 16; o; o >>= 1) rs += __shfl_xor_sync(~0u, rs, o);
        float inv = 1.0f / (rs + 1e-8f);
#pragma unroll
        for (int c = 0; c < 4; c++) {
            int off = lane + 32 * c;
            float4 o4;
            o4.x = tv[c].x * inv; o4.y = tv[c].y * inv;
            o4.z = tv[c].z * inv; o4.w = tv[c].w * inv;
            ((float4*)(T + base))[off] = o4;
            csum[c].x += o4.x; csum[c].y += o4.y;
            csum[c].z += o4.z; csum[c].w += o4.w;
        }
    }
#pragma unroll
    for (int c = 0; c < 4; c++) {
        int m = (lane + 32 * c) * 4;
        atomicAdd(&cs[m + 0], csum[c].x); atomicAdd(&cs[m + 1], csum[c].y);
        atomicAdd(&cs[m + 2], csum[c].z); atomicAdd(&cs[m + 3], csum[c].w);
    }
    __syncthreads();
    for (int i = t; i < 512; i += 256)
        atomicAdd(&g_colsum[b * 512 + i], cs[i]);
}

// ---------------- MI fused ----------------
__global__ void __launch_bounds__(256) mi_fused(float* __restrict__ T, int prev, int it) {
    __shared__ float inv[512];
    __shared__ float cs[512];
    int b = blockIdx.x >> 3, r0 = (blockIdx.x & 7) * 64;
    int t = threadIdx.x;
    for (int i = t; i < 512; i += 256) {
        inv[i] = 1.0f / (g_colsum[(size_t)prev * RQ + b * 512 + i] + 1e-8f);
        cs[i] = 0.f;
    }
    __syncthreads();
    int wid = t >> 5, lane = t & 31;
    float4 csum[4];
#pragma unroll
    for (int c = 0; c < 4; c++) csum[c] = make_float4(0.f, 0.f, 0.f, 0.f);
    for (int rr = wid; rr < 64; rr += 8) {
        int k = r0 + rr;
        size_t base = ((size_t)b * 512 + k) * 512;
        float4 tv[4];
        float rs = 0.f;
#pragma unroll
        for (int c = 0; c < 4; c++) {
            int off = lane + 32 * c;
            float4 x  = ((const float4*)(T + base))[off];
            float4 iv = ((const float4*)inv)[off];
            x.x *= iv.x; x.y *= iv.y; x.z *= iv.z; x.w *= iv.w;
            x.x *= x.x; x.y *= x.y; x.z *= x.z; x.w *= x.w;
            tv[c] = x;
            rs += x.x + x.y + x.z + x.w;
        }
#pragma unroll
        for (int o = 16; o; o >>= 1) rs += __shfl_xor_sync(~0u, rs, o);
        float rinv = 1.0f / (rs + 1e-8f);
#pragma unroll
        for (int c = 0; c < 4; c++) {
            int off = lane + 32 * c;
            float4 o4;
            o4.x = tv[c].x * rinv; o4.y = tv[c].y * rinv;
            o4.z = tv[c].z * rinv; o4.w = tv[c].w * rinv;
            ((float4*)(T + base))[off] = o4;
            csum[c].x += o4.x; csum[c].y += o4.y;
            csum[c].z += o4.z; csum[c].w += o4.w;
        }
    }
#pragma unroll
    for (int c = 0; c < 4; c++) {
        int m = (lane + 32 * c) * 4;
        atomicAdd(&cs[m + 0], csum[c].x); atomicAdd(&cs[m + 1], csum[c].y);
        atomicAdd(&cs[m + 2], csum[c].z); atomicAdd(&cs[m + 3], csum[c].w);
    }
    __syncthreads();
    for (int i = t; i < 512; i += 256)
        atomicAdd(&g_colsum[(size_t)it * RQ + b * 512 + i], cs[i]);
}

// ---------------- MI last ----------------
__global__ void __launch_bounds__(256) mi_last(float* __restrict__ T,
                                               const float* __restrict__ C,
                                               int last) {
    __shared__ float inv[512];
    __shared__ float red[8];
    int b = blockIdx.x >> 3, r0 = (blockIdx.x & 7) * 64;
    int t = threadIdx.x;
    for (int i = t; i < 512; i += 256)
        inv[i] = 1.0f / (g_colsum[(size_t)last * RQ + b * 512 + i] + 1e-8f);
    __syncthreads();
    int wid = t >> 5, lane = t & 31;
    float cacc = 0.f;
    for (int rr = wid; rr < 64; rr += 8) {
        int k = r0 + rr;
        size_t base = ((size_t)b * 512 + k) * 512;
#pragma unroll
        for (int c = 0; c < 4; c++) {
            int off = lane + 32 * c;
            float4 x  = ((const float4*)(T + base))[off];
            float4 iv = ((const float4*)inv)[off];
            x.x *= iv.x; x.y *= iv.y; x.z *= iv.z; x.w *= iv.w;
            ((float4*)(T + base))[off] = x;
            float4 cc = ((const float4*)(C + base))[off];
            cacc += x.x * cc.x + x.y * cc.y + x.z * cc.z + x.w * cc.w;
        }
    }
#pragma unroll
    for (int o = 16; o; o >>= 1) cacc += __shfl_xor_sync(~0u, cacc, o);
    if (lane == 0) red[wid] = cacc;
    __syncthreads();
    if (t == 0) {
        float s = 0.f;
#pragma unroll
        for (int w = 0; w < 8; w++) s += red[w];
        atomicAdd(&g_cvec[b], s);
    }
}

// ---------------- finalize ----------------
__global__ void finalize_kernel(float* __restrict__ sim, float* __restrict__ outc) {
    int b = threadIdx.x;
    if (b < BB) {
        float c = g_cvec[b];
        outc[b] = c;
        sim[b] = 1.0f / (1.0f + expf(c));
    }
}

// ---------------- launch ----------------
extern "C" void kernel_launch(void* const* d_in, const int* in_sizes, int n_in,
                              void* d_out, int out_size) {
    const float* sq = (const float*)d_in[0];
    const float* sr = (const float*)d_in[1];
    const float* mq = (const float*)d_in[2];
    const float* mr = (const float*)d_in[3];
    const float* W1 = (const float*)d_in[4];
    const float* b1 = (const float*)d_in[5];
    const float* W2 = (const float*)d_in[6];
    const float* b2 = (const float*)d_in[7];

    float* out = (float*)d_out;
    float* out_sim = out;
    float* out_T   = out + BB;
    float* out_C   = out + BB + TOTE;
    float* out_c   = out + BB + 2 * TOTE;

    float* Xt;  cudaGetSymbolAddress((void**)&Xt, g_Xt);
    float* Ht;  cudaGetSymbolAddress((void**)&Ht, g_Ht);
    float* Pt;  cudaGetSymbolAddress((void**)&Pt, g_Pt);
    float* W1t; cudaGetSymbolAddress((void**)&W1t, g_W1t);
    float* W2t; cudaGetSymbolAddress((void**)&W2t, g_W2t);

    prep_kernel<<<BB, 512>>>(mq, mr);

    // transposes to k-major
    transpose_k<<<dim3(RQ / 32, 8), 256>>>(sq, Xt, RTOT, 0);
    transpose_k<<<dim3(RQ / 32, 8), 256>>>(sr, Xt, RTOT, RQ);
    transpose_k<<<dim3(8, 8), 256>>>(W1, W1t, 256, 0);
    transpose_k<<<dim3(8, 8), 256>>>(W2, W2t, 256, 0);

    // layer 1: Ht = relu(W1 @ Xt + b1)  [feature][row]
    gemm_t<<<dim3(2, RTOT / 128), 256>>>(W1t, 256, Xt, RTOT, b1, Ht, 0);
    // layer 2: Pt = W2 @ Ht + b2, with row-norm atomics
    gemm_t<<<dim3(2, RTOT / 128), 256>>>(W2t, 256, Ht, RTOT, b2, Pt, 1);
    // cross distances
    gemm_t<<<dim3(4, 4, BB), 256>>>(Pt, RTOT, Pt, RTOT, nullptr, out_C, 2);

    ebuild_kernel<<<RQ / 8, 256>>>(out_C);

    sinkhorn_cluster<<<BB * 4, 256>>>();

    mi_first<<<BB * 8, 256>>>(out_T);
    mi_fused<<<BB * 8, 256>>>(out_T, 0, 1);
    mi_fused<<<BB * 8, 256>>>(out_T, 1, 2);
    mi_last<<<BB * 8, 256>>>(out_T, out_C, 2);

    finalize_kernel<<<1, 64>>>(out_sim, out_c);
}